// round 13
// baseline (speedup 1.0000x reference)
#include <cuda_runtime.h>
#include <cuda_fp16.h>
#include <cuda_fp8.h>
#include <cstddef>
#include <cstdint>

#define N_A   100000
#define N_P   150000
#define N_TOT (N_A + N_P)
#define D     128
#define C_OUT 16
#define EMAX  2000000
#define HSCALE 32.0f

// -------------------- device scratch (no allocs allowed) --------------------
// All node planes split into 2 feature chunks of 64 feats (128B fp16 / 64B fp8)
__device__ uint2 g_x16a  [(size_t)N_TOT * 16];
__device__ uint2 g_x16b  [(size_t)N_TOT * 16];
__device__ uint2 g_res16a[(size_t)N_TOT * 16];
__device__ uint2 g_res16b[(size_t)N_TOT * 16];
__device__ uint2 g_hA16a [(size_t)N_A * 16],  g_hA16b [(size_t)N_A * 16];
__device__ uint2 g_hP16a [(size_t)N_P * 16],  g_hP16b [(size_t)N_P * 16];
__device__ uint32_t g_hA8a[(size_t)N_A * 16], g_hA8b[(size_t)N_A * 16];
__device__ uint32_t g_hP8a[(size_t)N_P * 16], g_hP8b[(size_t)N_P * 16];
__device__ float g_W0c [D * D];
__device__ float g_W1c [D * D];
// CSR scratch (cnt zeroed by scatter2 each run; zero-init covers run #1)
__device__ int   g_cntA[N_A],     g_cntP[N_P];
__device__ int   g_rpA [N_A + 1], g_rpP [N_P + 1];
__device__ int   g_offA[N_A],     g_offP[N_P];
__device__ int   g_bsumA[256],    g_bsumP[256];
__device__ __align__(16) uint2 g_ecvA[EMAX];   // (col_local, val bits)
__device__ __align__(16) uint2 g_ecvP[EMAX];

// ----------------------------- fp16 / fp8 helpers ---------------------------
__device__ __forceinline__ float4 ldg_f16x4(const uint2* p) {
    uint2 r = __ldg(p);
    float2 a = __half22float2(*reinterpret_cast<const __half2*>(&r.x));
    float2 b = __half22float2(*reinterpret_cast<const __half2*>(&r.y));
    return make_float4(a.x, a.y, b.x, b.y);
}
__device__ __forceinline__ uint2 pack_f16x4(float4 v) {
    __half2 a = __floats2half2_rn(v.x, v.y);
    __half2 b = __floats2half2_rn(v.z, v.w);
    uint2 r;
    r.x = *reinterpret_cast<const uint32_t*>(&a);
    r.y = *reinterpret_cast<const uint32_t*>(&b);
    return r;
}
__device__ __forceinline__ uint32_t pack_fp8x4(float4 v) {
    __nv_fp8x2_storage_t lo = __nv_cvt_float2_to_fp8x2(make_float2(v.x, v.y),
                                                       __NV_SATFINITE, __NV_E4M3);
    __nv_fp8x2_storage_t hi = __nv_cvt_float2_to_fp8x2(make_float2(v.z, v.w),
                                                       __NV_SATFINITE, __NV_E4M3);
    return (uint32_t)lo | ((uint32_t)hi << 16);
}
__device__ __forceinline__ float4 fp8x4_to_float4(uint32_t u) {
    __half2_raw lo = __nv_cvt_fp8x2_to_halfraw2((__nv_fp8x2_storage_t)(u & 0xffffu), __NV_E4M3);
    __half2_raw hi = __nv_cvt_fp8x2_to_halfraw2((__nv_fp8x2_storage_t)(u >> 16),     __NV_E4M3);
    float2 a = __half22float2(*reinterpret_cast<const __half2*>(&lo));
    float2 b = __half22float2(*reinterpret_cast<const __half2*>(&hi));
    return make_float4(a.x, a.y, b.x, b.y);
}
__device__ __forceinline__ void accum16(float4& a, uint2 h, float v) {
    float2 f0 = __half22float2(*reinterpret_cast<const __half2*>(&h.x));
    float2 f1 = __half22float2(*reinterpret_cast<const __half2*>(&h.y));
    a.x += v * f0.x; a.y += v * f0.y; a.z += v * f1.x; a.w += v * f1.y;
}
__device__ __forceinline__ void accum8f(float4& a, uint32_t h, float v) {
    float4 f = fp8x4_to_float4(h);
    a.x += v * f.x; a.y += v * f.y; a.z += v * f.z; a.w += v * f.w;
}

// ------------ hop-1 gather over one 64-feat chunk (L2-resident src) ---------
// Half-warp edge pairing: lanes 0-15 edge i, lanes 16-31 edge i+1; lane lh
// owns feats 4lh..4lh+3 of the chunk (uint2 = 8B). 4 edges per iteration.
__device__ __forceinline__ float4 gather_h1(
    const uint2* __restrict__ ecv, const uint2* __restrict__ src,
    int s, int e, int half, int lh) {
    float4 a0 = {0, 0, 0, 0}, a1 = {0, 0, 0, 0};
    int i = s;
    if (i + 4 <= e) {
        uint2 pa = __ldg(&ecv[i + half]);
        uint2 pb = __ldg(&ecv[i + 2 + half]);
        for (; i + 8 <= e; i += 4) {
            uint2 na = __ldg(&ecv[i + 4 + half]);
            uint2 nb = __ldg(&ecv[i + 6 + half]);
            uint2 ha = __ldg(src + (size_t)pa.x * 16 + lh);
            uint2 hb = __ldg(src + (size_t)pb.x * 16 + lh);
            accum16(a0, ha, __uint_as_float(pa.y));
            accum16(a1, hb, __uint_as_float(pb.y));
            pa = na; pb = nb;
        }
        uint2 ha = __ldg(src + (size_t)pa.x * 16 + lh);
        uint2 hb = __ldg(src + (size_t)pb.x * 16 + lh);
        accum16(a0, ha, __uint_as_float(pa.y));
        accum16(a1, hb, __uint_as_float(pb.y));
        i += 4;
    }
    for (; i < e; i += 2) {
        int idx = i + half;
        uint2 p = __ldg(&ecv[idx < e ? idx : s]);
        float v = (idx < e) ? __uint_as_float(p.y) : 0.f;
        uint2 h = __ldg(src + (size_t)p.x * 16 + lh);
        accum16(a0, h, v);
    }
    a0.x += a1.x; a0.y += a1.y; a0.z += a1.z; a0.w += a1.w;
    a0.x += __shfl_xor_sync(0xffffffffu, a0.x, 16);
    a0.y += __shfl_xor_sync(0xffffffffu, a0.y, 16);
    a0.z += __shfl_xor_sync(0xffffffffu, a0.z, 16);
    a0.w += __shfl_xor_sync(0xffffffffu, a0.w, 16);
    return a0;
}

// ------------- hop-2 fp8 gather (chunked planes, full warp) ------------------
__device__ __forceinline__ float4 gather8(
    const uint2* __restrict__ ecv, const uint32_t* __restrict__ h8base,
    int s, int e, int lh16) {
    float4 a0 = {0, 0, 0, 0}, a1 = {0, 0, 0, 0};
    int i = s;
    if (i + 4 <= e) {
        uint2 p0 = __ldg(&ecv[i+0]), p1 = __ldg(&ecv[i+1]);
        uint2 p2 = __ldg(&ecv[i+2]), p3 = __ldg(&ecv[i+3]);
        for (; i + 8 <= e; i += 4) {
            uint2 n0 = __ldg(&ecv[i+4]), n1 = __ldg(&ecv[i+5]);
            uint2 n2 = __ldg(&ecv[i+6]), n3 = __ldg(&ecv[i+7]);
            uint32_t h0 = __ldg(h8base + (size_t)p0.x * 16 + lh16);
            uint32_t h1 = __ldg(h8base + (size_t)p1.x * 16 + lh16);
            uint32_t h2 = __ldg(h8base + (size_t)p2.x * 16 + lh16);
            uint32_t h3 = __ldg(h8base + (size_t)p3.x * 16 + lh16);
            accum8f(a0, h0, __uint_as_float(p0.y));
            accum8f(a1, h1, __uint_as_float(p1.y));
            accum8f(a0, h2, __uint_as_float(p2.y));
            accum8f(a1, h3, __uint_as_float(p3.y));
            p0 = n0; p1 = n1; p2 = n2; p3 = n3;
        }
        uint32_t h0 = __ldg(h8base + (size_t)p0.x * 16 + lh16);
        uint32_t h1 = __ldg(h8base + (size_t)p1.x * 16 + lh16);
        uint32_t h2 = __ldg(h8base + (size_t)p2.x * 16 + lh16);
        uint32_t h3 = __ldg(h8base + (size_t)p3.x * 16 + lh16);
        accum8f(a0, h0, __uint_as_float(p0.y));
        accum8f(a1, h1, __uint_as_float(p1.y));
        accum8f(a0, h2, __uint_as_float(p2.y));
        accum8f(a1, h3, __uint_as_float(p3.y));
        i += 4;
    }
    for (; i < e; i++) {
        uint2 p = __ldg(&ecv[i]);
        accum8f(a0, __ldg(h8base + (size_t)p.x * 16 + lh16), __uint_as_float(p.y));
    }
    a0.x += a1.x; a0.y += a1.y; a0.z += a1.z; a0.w += a1.w;
    return a0;
}

// -------------------- Wc = Wp @ W1 (both weights, one launch) ----------------
__global__ void __launch_bounds__(128) wcomb2_kernel(
    const float* __restrict__ Wp0, const float* __restrict__ Wp1,
    const float* __restrict__ W1,
    float* __restrict__ Wc0, float* __restrict__ Wc1) {
    __shared__ float srow[D];
    const float* Wp = (blockIdx.x < 128) ? Wp0 : Wp1;
    float*       Wc = (blockIdx.x < 128) ? Wc0 : Wc1;
    int r = blockIdx.x & 127;
    srow[threadIdx.x] = Wp[r * D + threadIdx.x];
    __syncthreads();
    float acc = 0.f;
    #pragma unroll 8
    for (int k = 0; k < D; k++)
        acc += srow[k] * __ldg(&W1[k * D + threadIdx.x]);
    Wc[r * D + threadIdx.x] = acc;
}

// ------------- fused projection GEMM + bias + relu + row-normalize ----------
__global__ void __launch_bounds__(256) proj_norm_kernel(
    const float* __restrict__ x0, const float* __restrict__ x1,
    const float* __restrict__ Wc0, const float* __restrict__ Wc1,
    const float* __restrict__ bias,
    uint2* __restrict__ xa, uint2* __restrict__ xb) {
    __shared__ float sA[64][128];
    __shared__ float sB[32][128];

    const int nblkA = (N_A + 63) / 64;
    const float* xin;
    const float* Wc;
    int row0, nrows, base_out;
    if ((int)blockIdx.x < nblkA) {
        xin = x0; Wc = Wc0; row0 = blockIdx.x * 64; nrows = N_A; base_out = 0;
    } else {
        xin = x1; Wc = Wc1; row0 = (blockIdx.x - nblkA) * 64; nrows = N_P; base_out = N_A;
    }
    const int tid = threadIdx.x;

    #pragma unroll
    for (int i = 0; i < 8; i++) {
        int idx = tid + i * 256;
        int r   = idx >> 5;
        int k4  = idx & 31;
        float4 v = make_float4(0.f, 0.f, 0.f, 0.f);
        if (row0 + r < nrows)
            v = __ldg((const float4*)(xin + (size_t)(row0 + r) * D) + k4);
        *(float4*)&sA[r][k4 * 4] = v;
    }

    const int tr = tid >> 5;
    const int tc = tid & 31;
    float acc[8][4];
    #pragma unroll
    for (int i = 0; i < 8; i++)
        #pragma unroll
        for (int j = 0; j < 4; j++) acc[i][j] = 0.f;

    for (int kc = 0; kc < 4; kc++) {
        __syncthreads();
        #pragma unroll
        for (int i = 0; i < 4; i++) {
            int idx = tid + i * 256;
            int kk  = idx >> 5;
            int c4  = idx & 31;
            *(float4*)&sB[kk][c4 * 4] =
                __ldg((const float4*)(Wc + (size_t)(kc * 32 + kk) * D) + c4);
        }
        __syncthreads();
        #pragma unroll
        for (int kk = 0; kk < 32; kk++) {
            float4 bv = *(float4*)&sB[kk][tc * 4];
            #pragma unroll
            for (int i = 0; i < 8; i++) {
                float a = sA[tr * 8 + i][kc * 32 + kk];
                acc[i][0] += a * bv.x; acc[i][1] += a * bv.y;
                acc[i][2] += a * bv.z; acc[i][3] += a * bv.w;
            }
        }
    }

    float4 bv = __ldg((const float4*)bias + tc);
    float bb[4] = {bv.x, bv.y, bv.z, bv.w};
    #pragma unroll
    for (int i = 0; i < 8; i++)
        #pragma unroll
        for (int j = 0; j < 4; j++) {
            float v = acc[i][j] + bb[j];
            acc[i][j] = v > 0.f ? v : 0.f;
        }

    #pragma unroll
    for (int i = 0; i < 8; i++) {
        float s = acc[i][0] + acc[i][1] + acc[i][2] + acc[i][3];
        float q = acc[i][0]*acc[i][0] + acc[i][1]*acc[i][1]
                + acc[i][2]*acc[i][2] + acc[i][3]*acc[i][3];
        #pragma unroll
        for (int o = 16; o; o >>= 1) {
            s += __shfl_xor_sync(0xffffffffu, s, o);
            q += __shfl_xor_sync(0xffffffffu, q, o);
        }
        float mean = s * (1.f / 128.f);
        float var  = (q - 128.f * mean * mean) * (1.f / 127.f);
        float rstd = (var > 0.f) ? rsqrtf(var) : 0.f;
        int r = row0 + tr * 8 + i;
        if (r < nrows) {
            size_t R = (size_t)(base_out + r);
            float4 o;
            o.x = (acc[i][0] - mean) * rstd;
            o.y = (acc[i][1] - mean) * rstd;
            o.z = (acc[i][2] - mean) * rstd;
            o.w = (acc[i][3] - mean) * rstd;
            if (tc < 16) xa[R * 16 + tc]        = pack_f16x4(o);
            else         xb[R * 16 + (tc - 16)] = pack_f16x4(o);
        }
    }
}

// ------------------------------ CSR build -----------------------------------
__global__ void __launch_bounds__(256) hist2_kernel(
    const int* __restrict__ rowsA, int E1, int* __restrict__ cntA,
    const int* __restrict__ rowsP, int E2, int* __restrict__ cntP) {
    int i = blockIdx.x * 256 + threadIdx.x;
    if (i < E1) atomicAdd(&cntA[__ldg(&rowsA[i])], 1);
    if (i < E2) atomicAdd(&cntP[__ldg(&rowsP[i]) - N_A], 1);
}

__global__ void __launch_bounds__(256) scan1_kernel(
    const int* __restrict__ cntA, int nA, int* __restrict__ rpA, int* __restrict__ bsumA, int nbA,
    const int* __restrict__ cntP, int nP, int* __restrict__ rpP, int* __restrict__ bsumP) {
    __shared__ int wsum[8];
    const int* cnt; int n; int* rp; int* bsum; int blk;
    if ((int)blockIdx.x < nbA) { cnt = cntA; n = nA; rp = rpA; bsum = bsumA; blk = blockIdx.x; }
    else                       { cnt = cntP; n = nP; rp = rpP; bsum = bsumP; blk = blockIdx.x - nbA; }
    const int base = blk * 2048;
    const int t = threadIdx.x;
    int v[8]; int s = 0;
    #pragma unroll
    for (int i = 0; i < 8; i++) {
        int idx = base + t * 8 + i;
        int c = (idx < n) ? __ldg(&cnt[idx]) : 0;
        v[i] = s; s += c;
    }
    int lane = t & 31, w = t >> 5;
    int p = s;
    #pragma unroll
    for (int o = 1; o < 32; o <<= 1) {
        int q = __shfl_up_sync(0xffffffffu, p, o);
        if (lane >= o) p += q;
    }
    if (lane == 31) wsum[w] = p;
    __syncthreads();
    if (t < 8) {
        int ws = wsum[t];
        int pp = ws;
        #pragma unroll
        for (int o = 1; o < 8; o <<= 1) {
            int q = __shfl_up_sync(0xffu, pp, o);
            if (t >= o) pp += q;
        }
        wsum[t] = pp - ws;
        if (t == 7) bsum[blk] = pp;
    }
    __syncthreads();
    int texcl = (p - s) + wsum[w];
    #pragma unroll
    for (int i = 0; i < 8; i++) {
        int idx = base + t * 8 + i;
        if (idx < n) rp[idx] = texcl + v[i];
    }
}

// scan3 with inline bsum prefix (merges old scan2): bsum holds RAW chunk totals
__global__ void __launch_bounds__(256) scan3m_kernel(
    const int* __restrict__ bsumA, int nA, int* __restrict__ rpA, int* __restrict__ offsA,
    const int* __restrict__ cntA, int ngA,
    const int* __restrict__ bsumP, int nP, int* __restrict__ rpP, int* __restrict__ offsP,
    const int* __restrict__ cntP) {
    __shared__ int s_pre;
    const int* bsum; int n; int* rp; int* offs; const int* cnt; int lb;
    if ((int)blockIdx.x < ngA) {
        bsum = bsumA; n = nA; rp = rpA; offs = offsA; cnt = cntA; lb = blockIdx.x;
    } else {
        bsum = bsumP; n = nP; rp = rpP; offs = offsP; cnt = cntP; lb = blockIdx.x - ngA;
    }
    int cidx = lb >> 3;   // bsum chunk index (2048 elems/chunk, 256/block)
    if (threadIdx.x < 32) {
        int acc = 0;
        for (int j = threadIdx.x; j < cidx; j += 32) acc += __ldg(&bsum[j]);
        #pragma unroll
        for (int o = 16; o; o >>= 1) acc += __shfl_xor_sync(0xffffffffu, acc, o);
        if (threadIdx.x == 0) s_pre = acc;
    }
    __syncthreads();
    int idx = lb * 256 + threadIdx.x;
    if (idx < n) {
        int v = rp[idx] + s_pre;
        rp[idx] = v;
        offs[idx] = v;
        if (idx == n - 1) rp[n] = v + __ldg(&cnt[idx]);
    }
}

// scatter + zero cnt for the next graph replay
__global__ void __launch_bounds__(256) scatter2_kernel(
    const int* __restrict__ rowsA, const int* __restrict__ colsA,
    const float* __restrict__ valsA, int E1, int* __restrict__ offsA, uint2* __restrict__ ecvA,
    int* __restrict__ cntA,
    const int* __restrict__ rowsP, const int* __restrict__ colsP,
    const float* __restrict__ valsP, int E2, int* __restrict__ offsP, uint2* __restrict__ ecvP,
    int* __restrict__ cntP) {
    int i = blockIdx.x * 256 + threadIdx.x;
    if (i < N_A) cntA[i] = 0;
    if (i < N_P) cntP[i] = 0;
    if (i < E1) {
        int r = __ldg(&rowsA[i]);
        int pos = atomicAdd(&offsA[r], 1);
        ecvA[pos] = make_uint2((unsigned)(__ldg(&colsA[i]) - N_A), __float_as_uint(__ldg(&valsA[i])));
    }
    if (i < E2) {
        int r = __ldg(&rowsP[i]) - N_A;
        int pos = atomicAdd(&offsP[r], 1);
        ecvP[pos] = make_uint2((unsigned)__ldg(&colsP[i]), __float_as_uint(__ldg(&valsP[i])));
    }
}

// -------------- hop-1 SpMM over ONE feature chunk (A + P merged) -------------
// src chunk plane is 64MB -> L2-resident. Writes fp16 + fp8 chunk planes.
__global__ void __launch_bounds__(256) spmm_hop1_chunk_kernel(
    const int* __restrict__ rpA, const uint2* __restrict__ ecvA,
    const uint2* __restrict__ srcA,    // x/res chunk plane, P-part base
    uint2* __restrict__ dstA16, uint32_t* __restrict__ dstA8,
    const int* __restrict__ rpP, const uint2* __restrict__ ecvP,
    const uint2* __restrict__ srcP,    // x/res chunk plane, A-part base
    uint2* __restrict__ dstP16, uint32_t* __restrict__ dstP8) {
    int g = (int)((blockIdx.x * 256u + threadIdx.x) >> 5);
    if (g >= N_TOT) return;
    int lane = threadIdx.x & 31, half = lane >> 4, lh = lane & 15;
    const int* rp; const uint2* ecv; const uint2* src; uint2* dst16; uint32_t* dst8; int r;
    if (g < N_A) { rp = rpA; ecv = ecvA; src = srcA; dst16 = dstA16; dst8 = dstA8; r = g; }
    else         { rp = rpP; ecv = ecvP; src = srcP; dst16 = dstP16; dst8 = dstP8; r = g - N_A; }
    int s = __ldg(&rp[r]), e = __ldg(&rp[r + 1]);
    float4 a = gather_h1(ecv, src, s, e, half, lh);
    if (half == 0) {
        dst16[(size_t)r * 16 + lh] = pack_f16x4(a);
        float4 as = make_float4(a.x * HSCALE, a.y * HSCALE, a.z * HSCALE, a.w * HSCALE);
        dst8[(size_t)r * 16 + lh] = pack_fp8x4(as);
    }
}

// ------------- merged pass-1 hop-2 fused with combine (A + P) ---------------
__global__ void __launch_bounds__(256) spmm_fused_kernel(
    const int* __restrict__ rpA, const uint2* __restrict__ ecvA,
    const int* __restrict__ rpP, const uint2* __restrict__ ecvP,
    const uint2* __restrict__ hA16a, const uint2* __restrict__ hA16b,
    const uint2* __restrict__ hP16a, const uint2* __restrict__ hP16b,
    const uint32_t* __restrict__ hA8a, const uint32_t* __restrict__ hA8b,
    const uint32_t* __restrict__ hP8a, const uint32_t* __restrict__ hP8b,
    const uint2* __restrict__ xa, const uint2* __restrict__ xb,
    uint2* __restrict__ resa, uint2* __restrict__ resb,
    const float* __restrict__ coe) {
    int g = (int)((blockIdx.x * 256u + threadIdx.x) >> 5);
    if (g >= N_TOT) return;
    int lane = threadIdx.x & 31;
    int lh16 = lane & 15;
    bool hiHalf = lane >= 16;
    const int* rp; const uint2* ecv; const uint32_t* h8; const uint2* hown;
    int r, c_own, c_hop;
    if (g < N_A) {
        rp = rpA; ecv = ecvA; r = g; c_own = 1; c_hop = 3;
        h8   = hiHalf ? hP8b  : hP8a;
        hown = hiHalf ? hA16b : hA16a;
    } else {
        rp = rpP; ecv = ecvP; r = g - N_A; c_own = 2; c_hop = 4;
        h8   = hiHalf ? hA8b  : hA8a;
        hown = hiHalf ? hP16b : hP16a;
    }
    int s = __ldg(&rp[r]), e = __ldg(&rp[r + 1]);
    float4 w = gather8(ecv, h8, s, e, lh16);

    size_t R = (size_t)g;
    float c0 = __ldg(&coe[0]);
    float cw = __ldg(&coe[c_own]);
    float ch = __ldg(&coe[c_hop]) * (1.0f / HSCALE);
    const uint2* xp = hiHalf ? xb : xa;
    float4 xv = ldg_f16x4(xp + R * 16 + lh16);
    float4 hv = ldg_f16x4(hown + (size_t)r * 16 + lh16);
    float4 o;
    o.x = c0 * xv.x + cw * hv.x + ch * w.x;
    o.y = c0 * xv.y + cw * hv.y + ch * w.y;
    o.z = c0 * xv.z + cw * hv.z + ch * w.z;
    o.w = c0 * xv.w + cw * hv.w + ch * w.w;
    uint2* rpout = hiHalf ? resb : resa;
    rpout[R * 16 + lh16] = pack_f16x4(o);
}

// ------ merged pass-2 hop-2 fused with combine AND output GEMM (A + P) -------
__global__ void __launch_bounds__(256) spmm_fused_out_kernel(
    const int* __restrict__ rpA, const uint2* __restrict__ ecvA,
    const int* __restrict__ rpP, const uint2* __restrict__ ecvP,
    const uint2* __restrict__ hA16a, const uint2* __restrict__ hA16b,
    const uint2* __restrict__ hP16a, const uint2* __restrict__ hP16b,
    const uint32_t* __restrict__ hA8a, const uint32_t* __restrict__ hA8b,
    const uint32_t* __restrict__ hP8a, const uint32_t* __restrict__ hP8b,
    const uint2* __restrict__ resa, const uint2* __restrict__ resb,
    float* __restrict__ out, const float* __restrict__ coe,
    const float* __restrict__ W2, const float* __restrict__ b2) {
    __shared__ float sW[C_OUT][D];
    __shared__ float sb2[C_OUT];
    int tid = threadIdx.x;
    for (int i = tid; i < C_OUT * D; i += 256) {
        int c = i >> 7, k = i & 127;
        sW[c][k] = __ldg(&W2[k * C_OUT + c]);
    }
    if (tid < C_OUT) sb2[tid] = __ldg(&b2[tid]);
    __syncthreads();

    int g = (int)((blockIdx.x * 256u + tid) >> 5);
    if (g >= N_TOT) return;
    int lane = tid & 31;
    int lh16 = lane & 15;
    bool hiHalf = lane >= 16;
    const int* rp; const uint2* ecv; const uint32_t* h8; const uint2* hown;
    int r, c_own, c_hop;
    if (g < N_A) {
        rp = rpA; ecv = ecvA; r = g; c_own = 2; c_hop = 4;
        h8   = hiHalf ? hP8b  : hP8a;
        hown = hiHalf ? hA16b : hA16a;
    } else {
        rp = rpP; ecv = ecvP; r = g - N_A; c_own = 1; c_hop = 3;
        h8   = hiHalf ? hA8b  : hA8a;
        hown = hiHalf ? hP16b : hP16a;
    }
    int s = __ldg(&rp[r]), e = __ldg(&rp[r + 1]);
    float4 w = gather8(ecv, h8, s, e, lh16);

    size_t R = (size_t)g;
    float c0 = __ldg(&coe[0]);
    float cw = __ldg(&coe[c_own]);
    float ch = __ldg(&coe[c_hop]) * (1.0f / HSCALE);
    const uint2* xp = hiHalf ? resb : resa;
    float4 xv = ldg_f16x4(xp + R * 16 + lh16);
    float4 hv = ldg_f16x4(hown + (size_t)r * 16 + lh16);
    float o0 = c0 * xv.x + cw * hv.x + ch * w.x;
    float o1 = c0 * xv.y + cw * hv.y + ch * w.y;
    float o2 = c0 * xv.z + cw * hv.z + ch * w.z;
    float o3 = c0 * xv.w + cw * hv.w + ch * w.w;

    // feature index of this lane: chunk offset + 4*lh16
    int f0 = (hiHalf ? 64 : 0) + lh16 * 4;
    float p[C_OUT];
    #pragma unroll
    for (int c = 0; c < C_OUT; c++) {
        float4 wv = *(const float4*)&sW[c][f0];
        p[c] = o0 * wv.x + o1 * wv.y + o2 * wv.z + o3 * wv.w;
    }
    #pragma unroll
    for (int off = 16; off; off >>= 1) {
        #pragma unroll
        for (int c = 0; c < C_OUT; c++)
            p[c] += __shfl_xor_sync(0xffffffffu, p[c], off);
    }
    if (lane < C_OUT)
        out[R * C_OUT + lane] = p[lane] + sb2[lane];
}

// ----------------------------------- launch ---------------------------------
extern "C" void kernel_launch(void* const* d_in, const int* in_sizes, int n_in,
                              void* d_out, int out_size) {
    const float* x0      = (const float*)d_in[0];
    const float* x1      = (const float*)d_in[1];
    const float* vals_ap = (const float*)d_in[2];
    const float* vals_pa = (const float*)d_in[3];
    const int*   rows_ap = (const int*)  d_in[4];
    const int*   cols_ap = (const int*)  d_in[5];
    const int*   rows_pa = (const int*)  d_in[6];
    const int*   cols_pa = (const int*)  d_in[7];
    const float* Wp0     = (const float*)d_in[8];
    const float* Wp1     = (const float*)d_in[9];
    const float* W1      = (const float*)d_in[10];
    const float* b1      = (const float*)d_in[11];
    const float* W2      = (const float*)d_in[12];
    const float* b2      = (const float*)d_in[13];
    const float* coe     = (const float*)d_in[14];
    float* out = (float*)d_out;

    const int E1 = in_sizes[2];
    const int E2 = in_sizes[3];

    float *pW0c, *pW1c;
    uint2 *pxa, *pxb, *presa, *presb;
    uint2 *phA16a, *phA16b, *phP16a, *phP16b, *pecvA, *pecvP;
    uint32_t *phA8a, *phA8b, *phP8a, *phP8b;
    int *pcntA, *pcntP, *prpA, *prpP, *poffA, *poffP, *pbA, *pbP;
    cudaGetSymbolAddress((void**)&pxa,    g_x16a);
    cudaGetSymbolAddress((void**)&pxb,    g_x16b);
    cudaGetSymbolAddress((void**)&presa,  g_res16a);
    cudaGetSymbolAddress((void**)&presb,  g_res16b);
    cudaGetSymbolAddress((void**)&phA16a, g_hA16a);
    cudaGetSymbolAddress((void**)&phA16b, g_hA16b);
    cudaGetSymbolAddress((void**)&phP16a, g_hP16a);
    cudaGetSymbolAddress((void**)&phP16b, g_hP16b);
    cudaGetSymbolAddress((void**)&phA8a,  g_hA8a);
    cudaGetSymbolAddress((void**)&phA8b,  g_hA8b);
    cudaGetSymbolAddress((void**)&phP8a,  g_hP8a);
    cudaGetSymbolAddress((void**)&phP8b,  g_hP8b);
    cudaGetSymbolAddress((void**)&pW0c,   g_W0c);
    cudaGetSymbolAddress((void**)&pW1c,   g_W1c);
    cudaGetSymbolAddress((void**)&pcntA,  g_cntA);
    cudaGetSymbolAddress((void**)&pcntP,  g_cntP);
    cudaGetSymbolAddress((void**)&prpA,   g_rpA);
    cudaGetSymbolAddress((void**)&prpP,   g_rpP);
    cudaGetSymbolAddress((void**)&poffA,  g_offA);
    cudaGetSymbolAddress((void**)&poffP,  g_offP);
    cudaGetSymbolAddress((void**)&pbA,    g_bsumA);
    cudaGetSymbolAddress((void**)&pbP,    g_bsumP);
    cudaGetSymbolAddress((void**)&pecvA,  g_ecvA);
    cudaGetSymbolAddress((void**)&pecvP,  g_ecvP);

    const int nbA = (N_A + 2047) / 2048;
    const int nbP = (N_P + 2047) / 2048;
    const int ngA = (N_A + 255) / 256;
    const int ngP = (N_P + 255) / 256;
    const int gT  = (int)(((size_t)N_TOT * 32 + 255) / 256);
    const int Emax = E1 > E2 ? E1 : E2;

    // 0) weight pre-combine + projection (chunked fp16 planes)
    wcomb2_kernel<<<2 * D, D>>>(Wp0, Wp1, W1, pW0c, pW1c);
    proj_norm_kernel<<<(N_A + 63) / 64 + (N_P + 63) / 64, 256>>>(
        x0, x1, pW0c, pW1c, b1, pxa, pxb);

    // 1) CSR build (scan2 merged into scan3m; cnt zeroed by scatter2)
    hist2_kernel<<<(Emax + 255) / 256, 256>>>(rows_ap, E1, pcntA, rows_pa, E2, pcntP);
    scan1_kernel<<<nbA + nbP, 256>>>(pcntA, N_A, prpA, pbA, nbA, pcntP, N_P, prpP, pbP);
    scan3m_kernel<<<ngA + ngP, 256>>>(pbA, N_A, prpA, poffA, pcntA, ngA,
                                      pbP, N_P, prpP, poffP, pcntP);
    scatter2_kernel<<<(Emax + 255) / 256, 256>>>(
        rows_ap, cols_ap, vals_ap, E1, poffA, pecvA, pcntA,
        rows_pa, cols_pa, vals_pa, E2, poffP, pecvP, pcntP);

    // ---------------- pass 1 (first_order = AP, PA) ----------------
    spmm_hop1_chunk_kernel<<<gT, 256>>>(prpA, pecvA, pxa + (size_t)N_A * 16, phA16a, phA8a,
                                        prpP, pecvP, pxa,                    phP16a, phP8a);
    spmm_hop1_chunk_kernel<<<gT, 256>>>(prpA, pecvA, pxb + (size_t)N_A * 16, phA16b, phA8b,
                                        prpP, pecvP, pxb,                    phP16b, phP8b);
    spmm_fused_kernel<<<gT, 256>>>(prpA, pecvA, prpP, pecvP,
                                   phA16a, phA16b, phP16a, phP16b,
                                   phA8a, phA8b, phP8a, phP8b,
                                   pxa, pxb, presa, presb, coe);

    // ---------------- pass 2 (first_order = PA, AP) ----------------
    spmm_hop1_chunk_kernel<<<gT, 256>>>(prpA, pecvA, presa + (size_t)N_A * 16, phA16a, phA8a,
                                        prpP, pecvP, presa,                    phP16a, phP8a);
    spmm_hop1_chunk_kernel<<<gT, 256>>>(prpA, pecvA, presb + (size_t)N_A * 16, phA16b, phA8b,
                                        prpP, pecvP, presb,                    phP16b, phP8b);
    spmm_fused_out_kernel<<<gT, 256>>>(prpA, pecvA, prpP, pecvP,
                                       phA16a, phA16b, phP16a, phP16b,
                                       phA8a, phA8b, phP8a, phP8b,
                                       presa, presb, out, coe, W2, b2);
}

// round 14
// speedup vs baseline: 1.2612x; 1.2612x over previous
#include <cuda_runtime.h>
#include <cuda_fp16.h>
#include <cuda_fp8.h>
#include <mma.h>
#include <cstddef>
#include <cstdint>

using namespace nvcuda;

#define N_A   100000
#define N_P   150000
#define N_TOT (N_A + N_P)
#define D     128
#define C_OUT 16
#define EMAX  2000000
#define HSCALE 32.0f

// -------------------- device scratch (no allocs allowed) --------------------
__device__ uint2 g_x16  [(size_t)N_TOT * 32];  // fp16x4 x plane
__device__ uint2 g_res16[(size_t)N_TOT * 32];  // fp16x4 res1 plane
__device__ uint2 g_hA16 [(size_t)N_A  * 32];   // fp16 hop-1 output (own-term plane)
__device__ uint2 g_hP16 [(size_t)N_P  * 32];
__device__ uint32_t g_hA8[(size_t)N_A * 32];   // fp8 e4m3 x HSCALE (hop-2 gather plane)
__device__ uint32_t g_hP8[(size_t)N_P * 32];
__device__ float g_W0c [D * D];
__device__ float g_W1c [D * D];
// CSR scratch (cnt zeroed by scatter2 each run; zero-init covers run #1)
__device__ int   g_cntA[N_A],     g_cntP[N_P];
__device__ int   g_rpA [N_A + 1], g_rpP [N_P + 1];
__device__ int   g_offA[N_A],     g_offP[N_P];
__device__ int   g_bsumA[256],    g_bsumP[256];
__device__ __align__(16) uint2 g_ecvA[EMAX];   // (col_local, val bits)
__device__ __align__(16) uint2 g_ecvP[EMAX];

// ----------------------------- fp16 / fp8 helpers ---------------------------
__device__ __forceinline__ float4 ldg_f16x4(const uint2* p) {
    uint2 r = __ldg(p);
    float2 a = __half22float2(*reinterpret_cast<const __half2*>(&r.x));
    float2 b = __half22float2(*reinterpret_cast<const __half2*>(&r.y));
    return make_float4(a.x, a.y, b.x, b.y);
}
__device__ __forceinline__ uint2 pack_f16x4(float4 v) {
    __half2 a = __floats2half2_rn(v.x, v.y);
    __half2 b = __floats2half2_rn(v.z, v.w);
    uint2 r;
    r.x = *reinterpret_cast<const uint32_t*>(&a);
    r.y = *reinterpret_cast<const uint32_t*>(&b);
    return r;
}
__device__ __forceinline__ uint32_t pack_fp8x4(float4 v) {
    __nv_fp8x2_storage_t lo = __nv_cvt_float2_to_fp8x2(make_float2(v.x, v.y),
                                                       __NV_SATFINITE, __NV_E4M3);
    __nv_fp8x2_storage_t hi = __nv_cvt_float2_to_fp8x2(make_float2(v.z, v.w),
                                                       __NV_SATFINITE, __NV_E4M3);
    return (uint32_t)lo | ((uint32_t)hi << 16);
}
__device__ __forceinline__ float4 fp8x4_to_float4(uint32_t u) {
    __half2_raw lo = __nv_cvt_fp8x2_to_halfraw2((__nv_fp8x2_storage_t)(u & 0xffffu), __NV_E4M3);
    __half2_raw hi = __nv_cvt_fp8x2_to_halfraw2((__nv_fp8x2_storage_t)(u >> 16),     __NV_E4M3);
    float2 a = __half22float2(*reinterpret_cast<const __half2*>(&lo));
    float2 b = __half22float2(*reinterpret_cast<const __half2*>(&hi));
    return make_float4(a.x, a.y, b.x, b.y);
}
__device__ __forceinline__ void accum16(float4& a, uint2 h, float v) {
    float2 f0 = __half22float2(*reinterpret_cast<const __half2*>(&h.x));
    float2 f1 = __half22float2(*reinterpret_cast<const __half2*>(&h.y));
    a.x += v * f0.x; a.y += v * f0.y; a.z += v * f1.x; a.w += v * f1.y;
}
__device__ __forceinline__ void accum8f(float4& a, uint32_t h, float v) {
    float4 f = fp8x4_to_float4(h);
    a.x += v * f.x; a.y += v * f.y; a.z += v * f.z; a.w += v * f.w;
}

// ------------------------- gather loops (MLP=4, prefetched) ------------------
__device__ __forceinline__ float4 gather16(
    const uint2* __restrict__ ecv, const uint2* __restrict__ src,
    int s, int e, int lane) {
    float4 a0 = {0, 0, 0, 0}, a1 = {0, 0, 0, 0};
    int i = s;
    if ((i & 1) && i < e) {
        uint2 p = __ldg(&ecv[i]);
        accum16(a0, __ldg(src + (size_t)p.x * 32 + lane), __uint_as_float(p.y));
        i++;
    }
    if (i + 4 <= e) {
        uint4 eAB = __ldg((const uint4*)(ecv + i));
        uint4 eCD = __ldg((const uint4*)(ecv + i + 2));
        for (; i + 8 <= e; i += 4) {
            uint4 nAB = __ldg((const uint4*)(ecv + i + 4));
            uint4 nCD = __ldg((const uint4*)(ecv + i + 6));
            uint2 h0 = __ldg(src + (size_t)eAB.x * 32 + lane);
            uint2 h1 = __ldg(src + (size_t)eAB.z * 32 + lane);
            uint2 h2 = __ldg(src + (size_t)eCD.x * 32 + lane);
            uint2 h3 = __ldg(src + (size_t)eCD.z * 32 + lane);
            accum16(a0, h0, __uint_as_float(eAB.y));
            accum16(a1, h1, __uint_as_float(eAB.w));
            accum16(a0, h2, __uint_as_float(eCD.y));
            accum16(a1, h3, __uint_as_float(eCD.w));
            eAB = nAB; eCD = nCD;
        }
        uint2 h0 = __ldg(src + (size_t)eAB.x * 32 + lane);
        uint2 h1 = __ldg(src + (size_t)eAB.z * 32 + lane);
        uint2 h2 = __ldg(src + (size_t)eCD.x * 32 + lane);
        uint2 h3 = __ldg(src + (size_t)eCD.z * 32 + lane);
        accum16(a0, h0, __uint_as_float(eAB.y));
        accum16(a1, h1, __uint_as_float(eAB.w));
        accum16(a0, h2, __uint_as_float(eCD.y));
        accum16(a1, h3, __uint_as_float(eCD.w));
        i += 4;
    }
    for (; i < e; i++) {
        uint2 p = __ldg(&ecv[i]);
        accum16(a0, __ldg(src + (size_t)p.x * 32 + lane), __uint_as_float(p.y));
    }
    a0.x += a1.x; a0.y += a1.y; a0.z += a1.z; a0.w += a1.w;
    return a0;
}

__device__ __forceinline__ float4 gather8(
    const uint2* __restrict__ ecv, const uint32_t* __restrict__ src,
    int s, int e, int lane) {
    float4 a0 = {0, 0, 0, 0}, a1 = {0, 0, 0, 0};
    int i = s;
    if ((i & 1) && i < e) {
        uint2 p = __ldg(&ecv[i]);
        accum8f(a0, __ldg(src + (size_t)p.x * 32 + lane), __uint_as_float(p.y));
        i++;
    }
    if (i + 4 <= e) {
        uint4 eAB = __ldg((const uint4*)(ecv + i));
        uint4 eCD = __ldg((const uint4*)(ecv + i + 2));
        for (; i + 8 <= e; i += 4) {
            uint4 nAB = __ldg((const uint4*)(ecv + i + 4));
            uint4 nCD = __ldg((const uint4*)(ecv + i + 6));
            uint32_t h0 = __ldg(src + (size_t)eAB.x * 32 + lane);
            uint32_t h1 = __ldg(src + (size_t)eAB.z * 32 + lane);
            uint32_t h2 = __ldg(src + (size_t)eCD.x * 32 + lane);
            uint32_t h3 = __ldg(src + (size_t)eCD.z * 32 + lane);
            accum8f(a0, h0, __uint_as_float(eAB.y));
            accum8f(a1, h1, __uint_as_float(eAB.w));
            accum8f(a0, h2, __uint_as_float(eCD.y));
            accum8f(a1, h3, __uint_as_float(eCD.w));
            eAB = nAB; eCD = nCD;
        }
        uint32_t h0 = __ldg(src + (size_t)eAB.x * 32 + lane);
        uint32_t h1 = __ldg(src + (size_t)eAB.z * 32 + lane);
        uint32_t h2 = __ldg(src + (size_t)eCD.x * 32 + lane);
        uint32_t h3 = __ldg(src + (size_t)eCD.z * 32 + lane);
        accum8f(a0, h0, __uint_as_float(eAB.y));
        accum8f(a1, h1, __uint_as_float(eAB.w));
        accum8f(a0, h2, __uint_as_float(eCD.y));
        accum8f(a1, h3, __uint_as_float(eCD.w));
        i += 4;
    }
    for (; i < e; i++) {
        uint2 p = __ldg(&ecv[i]);
        accum8f(a0, __ldg(src + (size_t)p.x * 32 + lane), __uint_as_float(p.y));
    }
    a0.x += a1.x; a0.y += a1.y; a0.z += a1.z; a0.w += a1.w;
    return a0;
}

// -------------------- Wc = Wp @ W1 (both weights, one launch) ----------------
__global__ void __launch_bounds__(128) wcomb2_kernel(
    const float* __restrict__ Wp0, const float* __restrict__ Wp1,
    const float* __restrict__ W1,
    float* __restrict__ Wc0, float* __restrict__ Wc1) {
    __shared__ float srow[D];
    const float* Wp = (blockIdx.x < 128) ? Wp0 : Wp1;
    float*       Wc = (blockIdx.x < 128) ? Wc0 : Wc1;
    int r = blockIdx.x & 127;
    srow[threadIdx.x] = Wp[r * D + threadIdx.x];
    __syncthreads();
    float acc = 0.f;
    #pragma unroll 8
    for (int k = 0; k < D; k++)
        acc += srow[k] * __ldg(&W1[k * D + threadIdx.x]);
    Wc[r * D + threadIdx.x] = acc;
}

// ----- tensor-core projection: y=relu(x@Wc+b) row-normalized -> fp16 plane ---
// 64-row x 128-col tile per block, 256 threads (8 warps), wmma m16n16k16.
// Dynamic smem: sX[64][144] fp16 (18.4KB) + sW[128][144] fp16 (36.9KB) = 55.3KB;
// fp32 out tile [64][136] (34.8KB) reuses the sW region after MMA.
#define LDX 144
#define LDO 136
#define PROJ_SMEM (64 * LDX * 2 + 128 * LDX * 2)
__global__ void __launch_bounds__(256) proj_norm_wmma_kernel(
    const float* __restrict__ x0, const float* __restrict__ x1,
    const float* __restrict__ Wc0, const float* __restrict__ Wc1,
    const float* __restrict__ bias, uint2* __restrict__ xout16) {
    extern __shared__ char smem[];
    __half* sX = (__half*)smem;                       // [64][LDX]
    __half* sW = (__half*)(smem + 64 * LDX * 2);      // [128][LDX]
    float*  sO = (float*)(smem + 64 * LDX * 2);       // [64][LDO], reuses sW

    const int nblkA = (N_A + 63) / 64;
    const float* xin;
    const float* Wc;
    int row0, nrows, base_out;
    if ((int)blockIdx.x < nblkA) {
        xin = x0; Wc = Wc0; row0 = blockIdx.x * 64; nrows = N_A; base_out = 0;
    } else {
        xin = x1; Wc = Wc1; row0 = (blockIdx.x - nblkA) * 64; nrows = N_P; base_out = N_A;
    }
    const int tid = threadIdx.x;

    // stage x tile (fp32 -> fp16), zero-padded past nrows
    for (int idx = tid; idx < 64 * 128; idx += 256) {
        int r = idx >> 7, c = idx & 127;
        float v = (row0 + r < nrows) ? __ldg(&xin[(size_t)(row0 + r) * D + c]) : 0.f;
        sX[r * LDX + c] = __float2half(v);
    }
    // stage Wc (fp32 -> fp16)
    for (int idx = tid; idx < 128 * 128; idx += 256) {
        int k = idx >> 7, n = idx & 127;
        sW[k * LDX + n] = __float2half(__ldg(&Wc[idx]));
    }
    __syncthreads();

    // MMA: warp (wm in 0..3, wn in 0..1) -> rows wm*16..+15, cols wn*64..+63
    const int warp = tid >> 5;
    const int wm = warp >> 1, wn = warp & 1;
    wmma::fragment<wmma::accumulator, 16, 16, 16, float> acc[4];
    #pragma unroll
    for (int j = 0; j < 4; j++) wmma::fill_fragment(acc[j], 0.f);
    #pragma unroll
    for (int k0 = 0; k0 < 8; k0++) {
        wmma::fragment<wmma::matrix_a, 16, 16, 16, __half, wmma::row_major> a;
        wmma::load_matrix_sync(a, sX + wm * 16 * LDX + k0 * 16, LDX);
        #pragma unroll
        for (int j = 0; j < 4; j++) {
            wmma::fragment<wmma::matrix_b, 16, 16, 16, __half, wmma::row_major> b;
            wmma::load_matrix_sync(b, sW + k0 * 16 * LDX + wn * 64 + j * 16, LDX);
            wmma::mma_sync(acc[j], a, b, acc[j]);
        }
    }
    __syncthreads();   // sW reads complete before sO overwrites the region
    #pragma unroll
    for (int j = 0; j < 4; j++)
        wmma::store_matrix_sync(sO + wm * 16 * LDO + wn * 64 + j * 16, acc[j],
                                LDO, wmma::mem_row_major);
    __syncthreads();

    // epilogue: warp w owns rows w*8..w*8+7; lane l owns cols 4l..4l+3
    const int lane = tid & 31;
    float4 bv = __ldg((const float4*)bias + lane);
    #pragma unroll
    for (int i = 0; i < 8; i++) {
        int row = warp * 8 + i;
        float4 v = *(const float4*)&sO[row * LDO + lane * 4];
        v.x += bv.x; v.y += bv.y; v.z += bv.z; v.w += bv.w;
        v.x = v.x > 0.f ? v.x : 0.f;
        v.y = v.y > 0.f ? v.y : 0.f;
        v.z = v.z > 0.f ? v.z : 0.f;
        v.w = v.w > 0.f ? v.w : 0.f;
        float s = v.x + v.y + v.z + v.w;
        float q = v.x * v.x + v.y * v.y + v.z * v.z + v.w * v.w;
        #pragma unroll
        for (int o = 16; o; o >>= 1) {
            s += __shfl_xor_sync(0xffffffffu, s, o);
            q += __shfl_xor_sync(0xffffffffu, q, o);
        }
        float mean = s * (1.f / 128.f);
        float var  = (q - 128.f * mean * mean) * (1.f / 127.f);
        float rstd = (var > 0.f) ? rsqrtf(var) : 0.f;
        int r = row0 + row;
        if (r < nrows) {
            size_t R = (size_t)(base_out + r);
            float4 o;
            o.x = (v.x - mean) * rstd;
            o.y = (v.y - mean) * rstd;
            o.z = (v.z - mean) * rstd;
            o.w = (v.w - mean) * rstd;
            xout16[R * 32 + lane] = pack_f16x4(o);
        }
    }
}

// ------------------------------ CSR build -----------------------------------
__global__ void __launch_bounds__(256) hist2_kernel(
    const int* __restrict__ rowsA, int E1, int* __restrict__ cntA,
    const int* __restrict__ rowsP, int E2, int* __restrict__ cntP) {
    int i = blockIdx.x * 256 + threadIdx.x;
    if (i < E1) atomicAdd(&cntA[__ldg(&rowsA[i])], 1);
    if (i < E2) atomicAdd(&cntP[__ldg(&rowsP[i]) - N_A], 1);
}

__global__ void __launch_bounds__(256) scan1_kernel(
    const int* __restrict__ cntA, int nA, int* __restrict__ rpA, int* __restrict__ bsumA, int nbA,
    const int* __restrict__ cntP, int nP, int* __restrict__ rpP, int* __restrict__ bsumP) {
    __shared__ int wsum[8];
    const int* cnt; int n; int* rp; int* bsum; int blk;
    if ((int)blockIdx.x < nbA) { cnt = cntA; n = nA; rp = rpA; bsum = bsumA; blk = blockIdx.x; }
    else                       { cnt = cntP; n = nP; rp = rpP; bsum = bsumP; blk = blockIdx.x - nbA; }
    const int base = blk * 2048;
    const int t = threadIdx.x;
    int v[8]; int s = 0;
    #pragma unroll
    for (int i = 0; i < 8; i++) {
        int idx = base + t * 8 + i;
        int c = (idx < n) ? __ldg(&cnt[idx]) : 0;
        v[i] = s; s += c;
    }
    int lane = t & 31, w = t >> 5;
    int p = s;
    #pragma unroll
    for (int o = 1; o < 32; o <<= 1) {
        int q = __shfl_up_sync(0xffffffffu, p, o);
        if (lane >= o) p += q;
    }
    if (lane == 31) wsum[w] = p;
    __syncthreads();
    if (t < 8) {
        int ws = wsum[t];
        int pp = ws;
        #pragma unroll
        for (int o = 1; o < 8; o <<= 1) {
            int q = __shfl_up_sync(0xffu, pp, o);
            if (t >= o) pp += q;
        }
        wsum[t] = pp - ws;
        if (t == 7) bsum[blk] = pp;
    }
    __syncthreads();
    int texcl = (p - s) + wsum[w];
    #pragma unroll
    for (int i = 0; i < 8; i++) {
        int idx = base + t * 8 + i;
        if (idx < n) rp[idx] = texcl + v[i];
    }
}

__global__ void __launch_bounds__(256) scan2_kernel(
    int* __restrict__ bsumA, int nbA, int* __restrict__ bsumP, int nbP) {
    __shared__ int sh[256];
    int* bsum = blockIdx.x == 0 ? bsumA : bsumP;
    int nb    = blockIdx.x == 0 ? nbA   : nbP;
    int t = threadIdx.x;
    int v = (t < nb) ? bsum[t] : 0;
    sh[t] = v; __syncthreads();
    #pragma unroll
    for (int o = 1; o < 256; o <<= 1) {
        int q = (t >= o) ? sh[t - o] : 0;
        __syncthreads();
        sh[t] += q;
        __syncthreads();
    }
    if (t < nb) bsum[t] = sh[t] - v;
}

__global__ void __launch_bounds__(256) scan3_kernel(
    const int* __restrict__ bsumA, int nA, int* __restrict__ rpA, int* __restrict__ offsA,
    const int* __restrict__ cntA, int ngA,
    const int* __restrict__ bsumP, int nP, int* __restrict__ rpP, int* __restrict__ offsP,
    const int* __restrict__ cntP) {
    const int* bsum; int n; int* rp; int* offs; const int* cnt; int idx;
    if ((int)blockIdx.x < ngA) {
        bsum = bsumA; n = nA; rp = rpA; offs = offsA; cnt = cntA;
        idx = blockIdx.x * 256 + threadIdx.x;
    } else {
        bsum = bsumP; n = nP; rp = rpP; offs = offsP; cnt = cntP;
        idx = (blockIdx.x - ngA) * 256 + threadIdx.x;
    }
    if (idx < n) {
        int v = rp[idx] + __ldg(&bsum[idx >> 11]);
        rp[idx] = v;
        offs[idx] = v;
        if (idx == n - 1) rp[n] = v + __ldg(&cnt[idx]);
    }
}

// scatter + zero cnt for the next graph replay
__global__ void __launch_bounds__(256) scatter2_kernel(
    const int* __restrict__ rowsA, const int* __restrict__ colsA,
    const float* __restrict__ valsA, int E1, int* __restrict__ offsA, uint2* __restrict__ ecvA,
    int* __restrict__ cntA,
    const int* __restrict__ rowsP, const int* __restrict__ colsP,
    const float* __restrict__ valsP, int E2, int* __restrict__ offsP, uint2* __restrict__ ecvP,
    int* __restrict__ cntP) {
    int i = blockIdx.x * 256 + threadIdx.x;
    if (i < N_A) cntA[i] = 0;
    if (i < N_P) cntP[i] = 0;
    if (i < E1) {
        int r = __ldg(&rowsA[i]);
        int pos = atomicAdd(&offsA[r], 1);
        ecvA[pos] = make_uint2((unsigned)(__ldg(&colsA[i]) - N_A), __float_as_uint(__ldg(&valsA[i])));
    }
    if (i < E2) {
        int r = __ldg(&rowsP[i]) - N_A;
        int pos = atomicAdd(&offsP[r], 1);
        ecvP[pos] = make_uint2((unsigned)__ldg(&colsP[i]), __float_as_uint(__ldg(&valsP[i])));
    }
}

// --------------------- merged hop-1 SpMM (A + P in one grid) -----------------
__global__ void __launch_bounds__(256) spmm_hop1_kernel(
    const int* __restrict__ rpA, const uint2* __restrict__ ecvA,
    const uint2* __restrict__ srcA, uint2* __restrict__ dstA16, uint32_t* __restrict__ dstA8,
    const int* __restrict__ rpP, const uint2* __restrict__ ecvP,
    const uint2* __restrict__ srcP, uint2* __restrict__ dstP16, uint32_t* __restrict__ dstP8) {
    int g = (int)((blockIdx.x * 256u + threadIdx.x) >> 5);
    if (g >= N_TOT) return;
    int lane = threadIdx.x & 31;
    const int* rp; const uint2* ecv; const uint2* src; uint2* dst16; uint32_t* dst8; int r;
    if (g < N_A) { rp = rpA; ecv = ecvA; src = srcA; dst16 = dstA16; dst8 = dstA8; r = g; }
    else         { rp = rpP; ecv = ecvP; src = srcP; dst16 = dstP16; dst8 = dstP8; r = g - N_A; }
    int s = __ldg(&rp[r]), e = __ldg(&rp[r + 1]);
    float4 a = gather16(ecv, src, s, e, lane);
    dst16[(size_t)r * 32 + lane] = pack_f16x4(a);
    float4 as = make_float4(a.x * HSCALE, a.y * HSCALE, a.z * HSCALE, a.w * HSCALE);
    dst8[(size_t)r * 32 + lane] = pack_fp8x4(as);
}

// ------------- merged pass-1 hop-2 fused with combine (A + P) ---------------
__global__ void __launch_bounds__(256) spmm_fused_kernel(
    const int* __restrict__ rpA, const uint2* __restrict__ ecvA,
    const int* __restrict__ rpP, const uint2* __restrict__ ecvP,
    const uint2* __restrict__ hA16, const uint2* __restrict__ hP16,
    const uint32_t* __restrict__ hA8, const uint32_t* __restrict__ hP8,
    const uint2* __restrict__ x16, uint2* __restrict__ res16,
    const float* __restrict__ coe) {
    int g = (int)((blockIdx.x * 256u + threadIdx.x) >> 5);
    if (g >= N_TOT) return;
    int lane = threadIdx.x & 31;
    const int* rp; const uint2* ecv; const uint32_t* hsrc8; const uint2* hown;
    int r, c_own, c_hop;
    if (g < N_A) { rp = rpA; ecv = ecvA; hsrc8 = hP8; hown = hA16; r = g;       c_own = 1; c_hop = 3; }
    else         { rp = rpP; ecv = ecvP; hsrc8 = hA8; hown = hP16; r = g - N_A; c_own = 2; c_hop = 4; }
    int s = __ldg(&rp[r]), e = __ldg(&rp[r + 1]);
    float4 w = gather8(ecv, hsrc8, s, e, lane);

    size_t R = (size_t)g;
    float c0 = __ldg(&coe[0]);
    float cw = __ldg(&coe[c_own]);
    float ch = __ldg(&coe[c_hop]) * (1.0f / HSCALE);
    float4 xv = ldg_f16x4(x16 + R * 32 + lane);
    float4 hv = ldg_f16x4(hown + (size_t)r * 32 + lane);
    float4 o;
    o.x = c0 * xv.x + cw * hv.x + ch * w.x;
    o.y = c0 * xv.y + cw * hv.y + ch * w.y;
    o.z = c0 * xv.z + cw * hv.z + ch * w.z;
    o.w = c0 * xv.w + cw * hv.w + ch * w.w;
    res16[R * 32 + lane] = pack_f16x4(o);
}

// ------ merged pass-2 hop-2 fused with combine AND output GEMM (A + P) -------
__global__ void __launch_bounds__(256) spmm_fused_out_kernel(
    const int* __restrict__ rpA, const uint2* __restrict__ ecvA,
    const int* __restrict__ rpP, const uint2* __restrict__ ecvP,
    const uint2* __restrict__ hA16, const uint2* __restrict__ hP16,
    const uint32_t* __restrict__ hA8, const uint32_t* __restrict__ hP8,
    const uint2* __restrict__ res16, float* __restrict__ out,
    const float* __restrict__ coe,
    const float* __restrict__ W2, const float* __restrict__ b2) {
    __shared__ float sW[C_OUT][D];
    __shared__ float sb2[C_OUT];
    int tid = threadIdx.x;
    for (int i = tid; i < C_OUT * D; i += 256) {
        int c = i >> 7, k = i & 127;
        sW[c][k] = __ldg(&W2[k * C_OUT + c]);
    }
    if (tid < C_OUT) sb2[tid] = __ldg(&b2[tid]);
    __syncthreads();

    int g = (int)((blockIdx.x * 256u + tid) >> 5);
    if (g >= N_TOT) return;
    int lane = tid & 31;
    const int* rp; const uint2* ecv; const uint32_t* hsrc8; const uint2* hown;
    int r, c_own, c_hop;
    if (g < N_A) { rp = rpA; ecv = ecvA; hsrc8 = hP8; hown = hA16; r = g;       c_own = 2; c_hop = 4; }
    else         { rp = rpP; ecv = ecvP; hsrc8 = hA8; hown = hP16; r = g - N_A; c_own = 1; c_hop = 3; }
    int s = __ldg(&rp[r]), e = __ldg(&rp[r + 1]);
    float4 w = gather8(ecv, hsrc8, s, e, lane);

    size_t R = (size_t)g;
    float c0 = __ldg(&coe[0]);
    float cw = __ldg(&coe[c_own]);
    float ch = __ldg(&coe[c_hop]) * (1.0f / HSCALE);
    float4 xv = ldg_f16x4(res16 + R * 32 + lane);
    float4 hv = ldg_f16x4(hown + (size_t)r * 32 + lane);
    float o0 = c0 * xv.x + cw * hv.x + ch * w.x;
    float o1 = c0 * xv.y + cw * hv.y + ch * w.y;
    float o2 = c0 * xv.z + cw * hv.z + ch * w.z;
    float o3 = c0 * xv.w + cw * hv.w + ch * w.w;

    float p[C_OUT];
    #pragma unroll
    for (int c = 0; c < C_OUT; c++) {
        float4 wv = *(const float4*)&sW[c][lane * 4];
        p[c] = o0 * wv.x + o1 * wv.y + o2 * wv.z + o3 * wv.w;
    }
    #pragma unroll
    for (int off = 16; off; off >>= 1) {
        #pragma unroll
        for (int c = 0; c < C_OUT; c++)
            p[c] += __shfl_xor_sync(0xffffffffu, p[c], off);
    }
    if (lane < C_OUT)
        out[R * C_OUT + lane] = p[lane] + sb2[lane];
}

// ----------------------------------- launch ---------------------------------
extern "C" void kernel_launch(void* const* d_in, const int* in_sizes, int n_in,
                              void* d_out, int out_size) {
    const float* x0      = (const float*)d_in[0];
    const float* x1      = (const float*)d_in[1];
    const float* vals_ap = (const float*)d_in[2];
    const float* vals_pa = (const float*)d_in[3];
    const int*   rows_ap = (const int*)  d_in[4];
    const int*   cols_ap = (const int*)  d_in[5];
    const int*   rows_pa = (const int*)  d_in[6];
    const int*   cols_pa = (const int*)  d_in[7];
    const float* Wp0     = (const float*)d_in[8];
    const float* Wp1     = (const float*)d_in[9];
    const float* W1      = (const float*)d_in[10];
    const float* b1      = (const float*)d_in[11];
    const float* W2      = (const float*)d_in[12];
    const float* b2      = (const float*)d_in[13];
    const float* coe     = (const float*)d_in[14];
    float* out = (float*)d_out;

    const int E1 = in_sizes[2];
    const int E2 = in_sizes[3];

    float *pW0c, *pW1c;
    uint2 *px16, *pres16, *phA16, *phP16, *pecvA, *pecvP;
    uint32_t *phA8, *phP8;
    int *pcntA, *pcntP, *prpA, *prpP, *poffA, *poffP, *pbA, *pbP;
    cudaGetSymbolAddress((void**)&px16,   g_x16);
    cudaGetSymbolAddress((void**)&pres16, g_res16);
    cudaGetSymbolAddress((void**)&phA16,  g_hA16);
    cudaGetSymbolAddress((void**)&phP16,  g_hP16);
    cudaGetSymbolAddress((void**)&phA8,   g_hA8);
    cudaGetSymbolAddress((void**)&phP8,   g_hP8);
    cudaGetSymbolAddress((void**)&pW0c,   g_W0c);
    cudaGetSymbolAddress((void**)&pW1c,   g_W1c);
    cudaGetSymbolAddress((void**)&pcntA,  g_cntA);
    cudaGetSymbolAddress((void**)&pcntP,  g_cntP);
    cudaGetSymbolAddress((void**)&prpA,   g_rpA);
    cudaGetSymbolAddress((void**)&prpP,   g_rpP);
    cudaGetSymbolAddress((void**)&poffA,  g_offA);
    cudaGetSymbolAddress((void**)&poffP,  g_offP);
    cudaGetSymbolAddress((void**)&pbA,    g_bsumA);
    cudaGetSymbolAddress((void**)&pbP,    g_bsumP);
    cudaGetSymbolAddress((void**)&pecvA,  g_ecvA);
    cudaGetSymbolAddress((void**)&pecvP,  g_ecvP);

    const int nbA = (N_A + 2047) / 2048;
    const int nbP = (N_P + 2047) / 2048;
    const int ngA = (N_A + 255) / 256;
    const int ngP = (N_P + 255) / 256;
    const int gT  = (int)(((size_t)N_TOT * 32 + 255) / 256);
    const int Emax = E1 > E2 ? E1 : E2;

    // 0) weight pre-combine + tensor-core projection
    cudaFuncSetAttribute(proj_norm_wmma_kernel,
                         cudaFuncAttributeMaxDynamicSharedMemorySize, PROJ_SMEM);
    wcomb2_kernel<<<2 * D, D>>>(Wp0, Wp1, W1, pW0c, pW1c);
    proj_norm_wmma_kernel<<<(N_A + 63) / 64 + (N_P + 63) / 64, 256, PROJ_SMEM>>>(
        x0, x1, pW0c, pW1c, b1, px16);

    // 1) CSR build (3-kernel scan; cnt zeroed by scatter2)
    hist2_kernel<<<(Emax + 255) / 256, 256>>>(rows_ap, E1, pcntA, rows_pa, E2, pcntP);
    scan1_kernel<<<nbA + nbP, 256>>>(pcntA, N_A, prpA, pbA, nbA, pcntP, N_P, prpP, pbP);
    scan2_kernel<<<2, 256>>>(pbA, nbA, pbP, nbP);
    scan3_kernel<<<ngA + ngP, 256>>>(pbA, N_A, prpA, poffA, pcntA, ngA,
                                     pbP, N_P, prpP, poffP, pcntP);
    scatter2_kernel<<<(Emax + 255) / 256, 256>>>(
        rows_ap, cols_ap, vals_ap, E1, poffA, pecvA, pcntA,
        rows_pa, cols_pa, vals_pa, E2, poffP, pecvP, pcntP);

    // ---------------- pass 1 (first_order = AP, PA) ----------------
    spmm_hop1_kernel<<<gT, 256>>>(prpA, pecvA, px16 + (size_t)N_A * 32, phA16, phA8,
                                  prpP, pecvP, px16,                    phP16, phP8);
    spmm_fused_kernel<<<gT, 256>>>(prpA, pecvA, prpP, pecvP,
                                   phA16, phP16, phA8, phP8,
                                   px16, pres16, coe);

    // ---------------- pass 2 (first_order = PA, AP) ----------------
    spmm_hop1_kernel<<<gT, 256>>>(prpA, pecvA, pres16 + (size_t)N_A * 32, phA16, phA8,
                                  prpP, pecvP, pres16,                    phP16, phP8);
    spmm_fused_out_kernel<<<gT, 256>>>(prpA, pecvA, prpP, pecvP,
                                       phA16, phP16, phA8, phP8,
                                       pres16, out, coe, W2, b2);
}

// round 15
// speedup vs baseline: 1.2751x; 1.0110x over previous
#include <cuda_runtime.h>
#include <cuda_fp16.h>
#include <cuda_fp8.h>
#include <mma.h>
#include <cstddef>
#include <cstdint>

using namespace nvcuda;

#define N_A   100000
#define N_P   150000
#define N_TOT (N_A + N_P)
#define D     128
#define C_OUT 16
#define EMAX  2000000
#define HSCALE 32.0f

// -------------------- device scratch (no allocs allowed) --------------------
__device__ uint2 g_x16  [(size_t)N_TOT * 32];  // fp16x4 x plane
__device__ uint2 g_res16[(size_t)N_TOT * 32];  // fp16x4 res1 plane
__device__ uint2 g_hA16 [(size_t)N_A  * 32];   // fp16 hop-1 output (own-term plane)
__device__ uint2 g_hP16 [(size_t)N_P  * 32];
__device__ uint32_t g_hA8[(size_t)N_A * 32];   // fp8 e4m3 x HSCALE (hop-2 gather plane)
__device__ uint32_t g_hP8[(size_t)N_P * 32];
__device__ float g_W0c [D * D];
__device__ float g_W1c [D * D];
// CSR scratch (cnt zeroed by scatter2 each run; zero-init covers run #1)
__device__ int   g_cntA[N_A],     g_cntP[N_P];
__device__ int   g_rpA [N_A + 1], g_rpP [N_P + 1];
__device__ int   g_offA[N_A],     g_offP[N_P];
__device__ int   g_bsumA[256],    g_bsumP[256];
__device__ __align__(16) uint2 g_ecvA[EMAX];   // (col_local, val bits)
__device__ __align__(16) uint2 g_ecvP[EMAX];

// ----------------------------- fp16 / fp8 helpers ---------------------------
__device__ __forceinline__ float4 ldg_f16x4(const uint2* p) {
    uint2 r = __ldg(p);
    float2 a = __half22float2(*reinterpret_cast<const __half2*>(&r.x));
    float2 b = __half22float2(*reinterpret_cast<const __half2*>(&r.y));
    return make_float4(a.x, a.y, b.x, b.y);
}
__device__ __forceinline__ uint2 pack_f16x4(float4 v) {
    __half2 a = __floats2half2_rn(v.x, v.y);
    __half2 b = __floats2half2_rn(v.z, v.w);
    uint2 r;
    r.x = *reinterpret_cast<const uint32_t*>(&a);
    r.y = *reinterpret_cast<const uint32_t*>(&b);
    return r;
}
__device__ __forceinline__ uint32_t pack_fp8x4(float4 v) {
    __nv_fp8x2_storage_t lo = __nv_cvt_float2_to_fp8x2(make_float2(v.x, v.y),
                                                       __NV_SATFINITE, __NV_E4M3);
    __nv_fp8x2_storage_t hi = __nv_cvt_float2_to_fp8x2(make_float2(v.z, v.w),
                                                       __NV_SATFINITE, __NV_E4M3);
    return (uint32_t)lo | ((uint32_t)hi << 16);
}
__device__ __forceinline__ float4 fp8x4_to_float4(uint32_t u) {
    __half2_raw lo = __nv_cvt_fp8x2_to_halfraw2((__nv_fp8x2_storage_t)(u & 0xffffu), __NV_E4M3);
    __half2_raw hi = __nv_cvt_fp8x2_to_halfraw2((__nv_fp8x2_storage_t)(u >> 16),     __NV_E4M3);
    float2 a = __half22float2(*reinterpret_cast<const __half2*>(&lo));
    float2 b = __half22float2(*reinterpret_cast<const __half2*>(&hi));
    return make_float4(a.x, a.y, b.x, b.y);
}
__device__ __forceinline__ void accum16(float4& a, uint2 h, float v) {
    float2 f0 = __half22float2(*reinterpret_cast<const __half2*>(&h.x));
    float2 f1 = __half22float2(*reinterpret_cast<const __half2*>(&h.y));
    a.x += v * f0.x; a.y += v * f0.y; a.z += v * f1.x; a.w += v * f1.y;
}
__device__ __forceinline__ void accum8f(float4& a, uint32_t h, float v) {
    float4 f = fp8x4_to_float4(h);
    a.x += v * f.x; a.y += v * f.y; a.z += v * f.z; a.w += v * f.w;
}

// ------------------------- gather loops (MLP=4, prefetched) ------------------
__device__ __forceinline__ float4 gather16(
    const uint2* __restrict__ ecv, const uint2* __restrict__ src,
    int s, int e, int lane) {
    float4 a0 = {0, 0, 0, 0}, a1 = {0, 0, 0, 0};
    int i = s;
    if ((i & 1) && i < e) {
        uint2 p = __ldg(&ecv[i]);
        accum16(a0, __ldg(src + (size_t)p.x * 32 + lane), __uint_as_float(p.y));
        i++;
    }
    if (i + 4 <= e) {
        uint4 eAB = __ldg((const uint4*)(ecv + i));
        uint4 eCD = __ldg((const uint4*)(ecv + i + 2));
        for (; i + 8 <= e; i += 4) {
            uint4 nAB = __ldg((const uint4*)(ecv + i + 4));
            uint4 nCD = __ldg((const uint4*)(ecv + i + 6));
            uint2 h0 = __ldg(src + (size_t)eAB.x * 32 + lane);
            uint2 h1 = __ldg(src + (size_t)eAB.z * 32 + lane);
            uint2 h2 = __ldg(src + (size_t)eCD.x * 32 + lane);
            uint2 h3 = __ldg(src + (size_t)eCD.z * 32 + lane);
            accum16(a0, h0, __uint_as_float(eAB.y));
            accum16(a1, h1, __uint_as_float(eAB.w));
            accum16(a0, h2, __uint_as_float(eCD.y));
            accum16(a1, h3, __uint_as_float(eCD.w));
            eAB = nAB; eCD = nCD;
        }
        uint2 h0 = __ldg(src + (size_t)eAB.x * 32 + lane);
        uint2 h1 = __ldg(src + (size_t)eAB.z * 32 + lane);
        uint2 h2 = __ldg(src + (size_t)eCD.x * 32 + lane);
        uint2 h3 = __ldg(src + (size_t)eCD.z * 32 + lane);
        accum16(a0, h0, __uint_as_float(eAB.y));
        accum16(a1, h1, __uint_as_float(eAB.w));
        accum16(a0, h2, __uint_as_float(eCD.y));
        accum16(a1, h3, __uint_as_float(eCD.w));
        i += 4;
    }
    for (; i < e; i++) {
        uint2 p = __ldg(&ecv[i]);
        accum16(a0, __ldg(src + (size_t)p.x * 32 + lane), __uint_as_float(p.y));
    }
    a0.x += a1.x; a0.y += a1.y; a0.z += a1.z; a0.w += a1.w;
    return a0;
}

__device__ __forceinline__ float4 gather8(
    const uint2* __restrict__ ecv, const uint32_t* __restrict__ src,
    int s, int e, int lane) {
    float4 a0 = {0, 0, 0, 0}, a1 = {0, 0, 0, 0};
    int i = s;
    if ((i & 1) && i < e) {
        uint2 p = __ldg(&ecv[i]);
        accum8f(a0, __ldg(src + (size_t)p.x * 32 + lane), __uint_as_float(p.y));
        i++;
    }
    if (i + 4 <= e) {
        uint4 eAB = __ldg((const uint4*)(ecv + i));
        uint4 eCD = __ldg((const uint4*)(ecv + i + 2));
        for (; i + 8 <= e; i += 4) {
            uint4 nAB = __ldg((const uint4*)(ecv + i + 4));
            uint4 nCD = __ldg((const uint4*)(ecv + i + 6));
            uint32_t h0 = __ldg(src + (size_t)eAB.x * 32 + lane);
            uint32_t h1 = __ldg(src + (size_t)eAB.z * 32 + lane);
            uint32_t h2 = __ldg(src + (size_t)eCD.x * 32 + lane);
            uint32_t h3 = __ldg(src + (size_t)eCD.z * 32 + lane);
            accum8f(a0, h0, __uint_as_float(eAB.y));
            accum8f(a1, h1, __uint_as_float(eAB.w));
            accum8f(a0, h2, __uint_as_float(eCD.y));
            accum8f(a1, h3, __uint_as_float(eCD.w));
            eAB = nAB; eCD = nCD;
        }
        uint32_t h0 = __ldg(src + (size_t)eAB.x * 32 + lane);
        uint32_t h1 = __ldg(src + (size_t)eAB.z * 32 + lane);
        uint32_t h2 = __ldg(src + (size_t)eCD.x * 32 + lane);
        uint32_t h3 = __ldg(src + (size_t)eCD.z * 32 + lane);
        accum8f(a0, h0, __uint_as_float(eAB.y));
        accum8f(a1, h1, __uint_as_float(eAB.w));
        accum8f(a0, h2, __uint_as_float(eCD.y));
        accum8f(a1, h3, __uint_as_float(eCD.w));
        i += 4;
    }
    for (; i < e; i++) {
        uint2 p = __ldg(&ecv[i]);
        accum8f(a0, __ldg(src + (size_t)p.x * 32 + lane), __uint_as_float(p.y));
    }
    a0.x += a1.x; a0.y += a1.y; a0.z += a1.z; a0.w += a1.w;
    return a0;
}

// -------------------- Wc = Wp @ W1 (both weights, one launch) ----------------
__global__ void __launch_bounds__(128) wcomb2_kernel(
    const float* __restrict__ Wp0, const float* __restrict__ Wp1,
    const float* __restrict__ W1,
    float* __restrict__ Wc0, float* __restrict__ Wc1) {
    __shared__ float srow[D];
    const float* Wp = (blockIdx.x < 128) ? Wp0 : Wp1;
    float*       Wc = (blockIdx.x < 128) ? Wc0 : Wc1;
    int r = blockIdx.x & 127;
    srow[threadIdx.x] = Wp[r * D + threadIdx.x];
    __syncthreads();
    float acc = 0.f;
    #pragma unroll 8
    for (int k = 0; k < D; k++)
        acc += srow[k] * __ldg(&W1[k * D + threadIdx.x]);
    Wc[r * D + threadIdx.x] = acc;
}

// ----- tensor-core projection: y=relu(x@Wc+b) row-normalized -> fp16 plane ---
#define LDX 144
#define LDO 136
#define PROJ_SMEM (64 * LDX * 2 + 128 * LDX * 2)
__global__ void __launch_bounds__(256) proj_norm_wmma_kernel(
    const float* __restrict__ x0, const float* __restrict__ x1,
    const float* __restrict__ Wc0, const float* __restrict__ Wc1,
    const float* __restrict__ bias, uint2* __restrict__ xout16) {
    extern __shared__ char smem[];
    __half* sX = (__half*)smem;                       // [64][LDX]
    __half* sW = (__half*)(smem + 64 * LDX * 2);      // [128][LDX]
    float*  sO = (float*)(smem + 64 * LDX * 2);       // [64][LDO], reuses sW

    const int nblkA = (N_A + 63) / 64;
    const float* xin;
    const float* Wc;
    int row0, nrows, base_out;
    if ((int)blockIdx.x < nblkA) {
        xin = x0; Wc = Wc0; row0 = blockIdx.x * 64; nrows = N_A; base_out = 0;
    } else {
        xin = x1; Wc = Wc1; row0 = (blockIdx.x - nblkA) * 64; nrows = N_P; base_out = N_A;
    }
    const int tid = threadIdx.x;

    for (int idx = tid; idx < 64 * 128; idx += 256) {
        int r = idx >> 7, c = idx & 127;
        float v = (row0 + r < nrows) ? __ldg(&xin[(size_t)(row0 + r) * D + c]) : 0.f;
        sX[r * LDX + c] = __float2half(v);
    }
    for (int idx = tid; idx < 128 * 128; idx += 256) {
        int k = idx >> 7, n = idx & 127;
        sW[k * LDX + n] = __float2half(__ldg(&Wc[idx]));
    }
    __syncthreads();

    const int warp = tid >> 5;
    const int wm = warp >> 1, wn = warp & 1;
    wmma::fragment<wmma::accumulator, 16, 16, 16, float> acc[4];
    #pragma unroll
    for (int j = 0; j < 4; j++) wmma::fill_fragment(acc[j], 0.f);
    #pragma unroll
    for (int k0 = 0; k0 < 8; k0++) {
        wmma::fragment<wmma::matrix_a, 16, 16, 16, __half, wmma::row_major> a;
        wmma::load_matrix_sync(a, sX + wm * 16 * LDX + k0 * 16, LDX);
        #pragma unroll
        for (int j = 0; j < 4; j++) {
            wmma::fragment<wmma::matrix_b, 16, 16, 16, __half, wmma::row_major> b;
            wmma::load_matrix_sync(b, sW + k0 * 16 * LDX + wn * 64 + j * 16, LDX);
            wmma::mma_sync(acc[j], a, b, acc[j]);
        }
    }
    __syncthreads();
    #pragma unroll
    for (int j = 0; j < 4; j++)
        wmma::store_matrix_sync(sO + wm * 16 * LDO + wn * 64 + j * 16, acc[j],
                                LDO, wmma::mem_row_major);
    __syncthreads();

    const int lane = tid & 31;
    float4 bv = __ldg((const float4*)bias + lane);
    #pragma unroll
    for (int i = 0; i < 8; i++) {
        int row = warp * 8 + i;
        float4 v = *(const float4*)&sO[row * LDO + lane * 4];
        v.x += bv.x; v.y += bv.y; v.z += bv.z; v.w += bv.w;
        v.x = v.x > 0.f ? v.x : 0.f;
        v.y = v.y > 0.f ? v.y : 0.f;
        v.z = v.z > 0.f ? v.z : 0.f;
        v.w = v.w > 0.f ? v.w : 0.f;
        float s = v.x + v.y + v.z + v.w;
        float q = v.x * v.x + v.y * v.y + v.z * v.z + v.w * v.w;
        #pragma unroll
        for (int o = 16; o; o >>= 1) {
            s += __shfl_xor_sync(0xffffffffu, s, o);
            q += __shfl_xor_sync(0xffffffffu, q, o);
        }
        float mean = s * (1.f / 128.f);
        float var  = (q - 128.f * mean * mean) * (1.f / 127.f);
        float rstd = (var > 0.f) ? rsqrtf(var) : 0.f;
        int r = row0 + row;
        if (r < nrows) {
            size_t R = (size_t)(base_out + r);
            float4 o;
            o.x = (v.x - mean) * rstd;
            o.y = (v.y - mean) * rstd;
            o.z = (v.z - mean) * rstd;
            o.w = (v.w - mean) * rstd;
            xout16[R * 32 + lane] = pack_f16x4(o);
        }
    }
}

// ------------------------------ CSR build -----------------------------------
__global__ void __launch_bounds__(256) hist2_kernel(
    const int* __restrict__ rowsA, int E1, int* __restrict__ cntA,
    const int* __restrict__ rowsP, int E2, int* __restrict__ cntP) {
    int i = blockIdx.x * 256 + threadIdx.x;
    if (i < E1) atomicAdd(&cntA[__ldg(&rowsA[i])], 1);
    if (i < E2) atomicAdd(&cntP[__ldg(&rowsP[i]) - N_A], 1);
}

__global__ void __launch_bounds__(256) scan1_kernel(
    const int* __restrict__ cntA, int nA, int* __restrict__ rpA, int* __restrict__ bsumA, int nbA,
    const int* __restrict__ cntP, int nP, int* __restrict__ rpP, int* __restrict__ bsumP) {
    __shared__ int wsum[8];
    const int* cnt; int n; int* rp; int* bsum; int blk;
    if ((int)blockIdx.x < nbA) { cnt = cntA; n = nA; rp = rpA; bsum = bsumA; blk = blockIdx.x; }
    else                       { cnt = cntP; n = nP; rp = rpP; bsum = bsumP; blk = blockIdx.x - nbA; }
    const int base = blk * 2048;
    const int t = threadIdx.x;
    int v[8]; int s = 0;
    #pragma unroll
    for (int i = 0; i < 8; i++) {
        int idx = base + t * 8 + i;
        int c = (idx < n) ? __ldg(&cnt[idx]) : 0;
        v[i] = s; s += c;
    }
    int lane = t & 31, w = t >> 5;
    int p = s;
    #pragma unroll
    for (int o = 1; o < 32; o <<= 1) {
        int q = __shfl_up_sync(0xffffffffu, p, o);
        if (lane >= o) p += q;
    }
    if (lane == 31) wsum[w] = p;
    __syncthreads();
    if (t < 8) {
        int ws = wsum[t];
        int pp = ws;
        #pragma unroll
        for (int o = 1; o < 8; o <<= 1) {
            int q = __shfl_up_sync(0xffu, pp, o);
            if (t >= o) pp += q;
        }
        wsum[t] = pp - ws;
        if (t == 7) bsum[blk] = pp;
    }
    __syncthreads();
    int texcl = (p - s) + wsum[w];
    #pragma unroll
    for (int i = 0; i < 8; i++) {
        int idx = base + t * 8 + i;
        if (idx < n) rp[idx] = texcl + v[i];
    }
}

__global__ void __launch_bounds__(256) scan2_kernel(
    int* __restrict__ bsumA, int nbA, int* __restrict__ bsumP, int nbP) {
    __shared__ int sh[256];
    int* bsum = blockIdx.x == 0 ? bsumA : bsumP;
    int nb    = blockIdx.x == 0 ? nbA   : nbP;
    int t = threadIdx.x;
    int v = (t < nb) ? bsum[t] : 0;
    sh[t] = v; __syncthreads();
    #pragma unroll
    for (int o = 1; o < 256; o <<= 1) {
        int q = (t >= o) ? sh[t - o] : 0;
        __syncthreads();
        sh[t] += q;
        __syncthreads();
    }
    if (t < nb) bsum[t] = sh[t] - v;
}

__global__ void __launch_bounds__(256) scan3_kernel(
    const int* __restrict__ bsumA, int nA, int* __restrict__ rpA, int* __restrict__ offsA,
    const int* __restrict__ cntA, int ngA,
    const int* __restrict__ bsumP, int nP, int* __restrict__ rpP, int* __restrict__ offsP,
    const int* __restrict__ cntP) {
    const int* bsum; int n; int* rp; int* offs; const int* cnt; int idx;
    if ((int)blockIdx.x < ngA) {
        bsum = bsumA; n = nA; rp = rpA; offs = offsA; cnt = cntA;
        idx = blockIdx.x * 256 + threadIdx.x;
    } else {
        bsum = bsumP; n = nP; rp = rpP; offs = offsP; cnt = cntP;
        idx = (blockIdx.x - ngA) * 256 + threadIdx.x;
    }
    if (idx < n) {
        int v = rp[idx] + __ldg(&bsum[idx >> 11]);
        rp[idx] = v;
        offs[idx] = v;
        if (idx == n - 1) rp[n] = v + __ldg(&cnt[idx]);
    }
}

// scatter + zero cnt for the next graph replay
__global__ void __launch_bounds__(256) scatter2_kernel(
    const int* __restrict__ rowsA, const int* __restrict__ colsA,
    const float* __restrict__ valsA, int E1, int* __restrict__ offsA, uint2* __restrict__ ecvA,
    int* __restrict__ cntA,
    const int* __restrict__ rowsP, const int* __restrict__ colsP,
    const float* __restrict__ valsP, int E2, int* __restrict__ offsP, uint2* __restrict__ ecvP,
    int* __restrict__ cntP) {
    int i = blockIdx.x * 256 + threadIdx.x;
    if (i < N_A) cntA[i] = 0;
    if (i < N_P) cntP[i] = 0;
    if (i < E1) {
        int r = __ldg(&rowsA[i]);
        int pos = atomicAdd(&offsA[r], 1);
        ecvA[pos] = make_uint2((unsigned)(__ldg(&colsA[i]) - N_A), __float_as_uint(__ldg(&valsA[i])));
    }
    if (i < E2) {
        int r = __ldg(&rowsP[i]) - N_A;
        int pos = atomicAdd(&offsP[r], 1);
        ecvP[pos] = make_uint2((unsigned)__ldg(&colsP[i]), __float_as_uint(__ldg(&valsP[i])));
    }
}

// --------------------- merged hop-1 SpMM (A + P in one grid) -----------------
__global__ void __launch_bounds__(256) spmm_hop1_kernel(
    const int* __restrict__ rpA, const uint2* __restrict__ ecvA,
    const uint2* __restrict__ srcA, uint2* __restrict__ dstA16, uint32_t* __restrict__ dstA8,
    const int* __restrict__ rpP, const uint2* __restrict__ ecvP,
    const uint2* __restrict__ srcP, uint2* __restrict__ dstP16, uint32_t* __restrict__ dstP8) {
    int g = (int)((blockIdx.x * 256u + threadIdx.x) >> 5);
    if (g >= N_TOT) return;
    int lane = threadIdx.x & 31;
    const int* rp; const uint2* ecv; const uint2* src; uint2* dst16; uint32_t* dst8; int r;
    if (g < N_A) { rp = rpA; ecv = ecvA; src = srcA; dst16 = dstA16; dst8 = dstA8; r = g; }
    else         { rp = rpP; ecv = ecvP; src = srcP; dst16 = dstP16; dst8 = dstP8; r = g - N_A; }
    int s = __ldg(&rp[r]), e = __ldg(&rp[r + 1]);
    float4 a = gather16(ecv, src, s, e, lane);
    dst16[(size_t)r * 32 + lane] = pack_f16x4(a);
    float4 as = make_float4(a.x * HSCALE, a.y * HSCALE, a.z * HSCALE, a.w * HSCALE);
    dst8[(size_t)r * 32 + lane] = pack_fp8x4(as);
}

// ------------- merged pass-1 hop-2 fused with combine (A + P) ---------------
__global__ void __launch_bounds__(256) spmm_fused_kernel(
    const int* __restrict__ rpA, const uint2* __restrict__ ecvA,
    const int* __restrict__ rpP, const uint2* __restrict__ ecvP,
    const uint2* __restrict__ hA16, const uint2* __restrict__ hP16,
    const uint32_t* __restrict__ hA8, const uint32_t* __restrict__ hP8,
    const uint2* __restrict__ x16, uint2* __restrict__ res16,
    const float* __restrict__ coe) {
    int g = (int)((blockIdx.x * 256u + threadIdx.x) >> 5);
    if (g >= N_TOT) return;
    int lane = threadIdx.x & 31;
    const int* rp; const uint2* ecv; const uint32_t* hsrc8; const uint2* hown;
    int r, c_own, c_hop;
    if (g < N_A) { rp = rpA; ecv = ecvA; hsrc8 = hP8; hown = hA16; r = g;       c_own = 1; c_hop = 3; }
    else         { rp = rpP; ecv = ecvP; hsrc8 = hA8; hown = hP16; r = g - N_A; c_own = 2; c_hop = 4; }
    int s = __ldg(&rp[r]), e = __ldg(&rp[r + 1]);
    float4 w = gather8(ecv, hsrc8, s, e, lane);

    size_t R = (size_t)g;
    float c0 = __ldg(&coe[0]);
    float cw = __ldg(&coe[c_own]);
    float ch = __ldg(&coe[c_hop]) * (1.0f / HSCALE);
    float4 xv = ldg_f16x4(x16 + R * 32 + lane);
    float4 hv = ldg_f16x4(hown + (size_t)r * 32 + lane);
    float4 o;
    o.x = c0 * xv.x + cw * hv.x + ch * w.x;
    o.y = c0 * xv.y + cw * hv.y + ch * w.y;
    o.z = c0 * xv.z + cw * hv.z + ch * w.z;
    o.w = c0 * xv.w + cw * hv.w + ch * w.w;
    res16[R * 32 + lane] = pack_f16x4(o);
}

// ------ merged pass-2 hop-2 fused with combine AND output GEMM (A + P) -------
__global__ void __launch_bounds__(256) spmm_fused_out_kernel(
    const int* __restrict__ rpA, const uint2* __restrict__ ecvA,
    const int* __restrict__ rpP, const uint2* __restrict__ ecvP,
    const uint2* __restrict__ hA16, const uint2* __restrict__ hP16,
    const uint32_t* __restrict__ hA8, const uint32_t* __restrict__ hP8,
    const uint2* __restrict__ res16, float* __restrict__ out,
    const float* __restrict__ coe,
    const float* __restrict__ W2, const float* __restrict__ b2) {
    __shared__ float sW[C_OUT][D];
    __shared__ float sb2[C_OUT];
    int tid = threadIdx.x;
    for (int i = tid; i < C_OUT * D; i += 256) {
        int c = i >> 7, k = i & 127;
        sW[c][k] = __ldg(&W2[k * C_OUT + c]);
    }
    if (tid < C_OUT) sb2[tid] = __ldg(&b2[tid]);
    __syncthreads();

    int g = (int)((blockIdx.x * 256u + tid) >> 5);
    if (g >= N_TOT) return;
    int lane = tid & 31;
    const int* rp; const uint2* ecv; const uint32_t* hsrc8; const uint2* hown;
    int r, c_own, c_hop;
    if (g < N_A) { rp = rpA; ecv = ecvA; hsrc8 = hP8; hown = hA16; r = g;       c_own = 2; c_hop = 4; }
    else         { rp = rpP; ecv = ecvP; hsrc8 = hA8; hown = hP16; r = g - N_A; c_own = 1; c_hop = 3; }
    int s = __ldg(&rp[r]), e = __ldg(&rp[r + 1]);
    float4 w = gather8(ecv, hsrc8, s, e, lane);

    size_t R = (size_t)g;
    float c0 = __ldg(&coe[0]);
    float cw = __ldg(&coe[c_own]);
    float ch = __ldg(&coe[c_hop]) * (1.0f / HSCALE);
    float4 xv = ldg_f16x4(res16 + R * 32 + lane);
    float4 hv = ldg_f16x4(hown + (size_t)r * 32 + lane);
    float o0 = c0 * xv.x + cw * hv.x + ch * w.x;
    float o1 = c0 * xv.y + cw * hv.y + ch * w.y;
    float o2 = c0 * xv.z + cw * hv.z + ch * w.z;
    float o3 = c0 * xv.w + cw * hv.w + ch * w.w;

    float p[C_OUT];
    #pragma unroll
    for (int c = 0; c < C_OUT; c++) {
        float4 wv = *(const float4*)&sW[c][lane * 4];
        p[c] = o0 * wv.x + o1 * wv.y + o2 * wv.z + o3 * wv.w;
    }
    #pragma unroll
    for (int off = 16; off; off >>= 1) {
        #pragma unroll
        for (int c = 0; c < C_OUT; c++)
            p[c] += __shfl_xor_sync(0xffffffffu, p[c], off);
    }
    if (lane < C_OUT)
        out[R * C_OUT + lane] = p[lane] + sb2[lane];
}

// ----------------------------------- launch ---------------------------------
extern "C" void kernel_launch(void* const* d_in, const int* in_sizes, int n_in,
                              void* d_out, int out_size) {
    const float* x0      = (const float*)d_in[0];
    const float* x1      = (const float*)d_in[1];
    const float* vals_ap = (const float*)d_in[2];
    const float* vals_pa = (const float*)d_in[3];
    const int*   rows_ap = (const int*)  d_in[4];
    const int*   cols_ap = (const int*)  d_in[5];
    const int*   rows_pa = (const int*)  d_in[6];
    const int*   cols_pa = (const int*)  d_in[7];
    const float* Wp0     = (const float*)d_in[8];
    const float* Wp1     = (const float*)d_in[9];
    const float* W1      = (const float*)d_in[10];
    const float* b1      = (const float*)d_in[11];
    const float* W2      = (const float*)d_in[12];
    const float* b2      = (const float*)d_in[13];
    const float* coe     = (const float*)d_in[14];
    float* out = (float*)d_out;

    const int E1 = in_sizes[2];
    const int E2 = in_sizes[3];

    float *pW0c, *pW1c;
    uint2 *px16, *pres16, *phA16, *phP16, *pecvA, *pecvP;
    uint32_t *phA8, *phP8;
    int *pcntA, *pcntP, *prpA, *prpP, *poffA, *poffP, *pbA, *pbP;
    cudaGetSymbolAddress((void**)&px16,   g_x16);
    cudaGetSymbolAddress((void**)&pres16, g_res16);
    cudaGetSymbolAddress((void**)&phA16,  g_hA16);
    cudaGetSymbolAddress((void**)&phP16,  g_hP16);
    cudaGetSymbolAddress((void**)&phA8,   g_hA8);
    cudaGetSymbolAddress((void**)&phP8,   g_hP8);
    cudaGetSymbolAddress((void**)&pW0c,   g_W0c);
    cudaGetSymbolAddress((void**)&pW1c,   g_W1c);
    cudaGetSymbolAddress((void**)&pcntA,  g_cntA);
    cudaGetSymbolAddress((void**)&pcntP,  g_cntP);
    cudaGetSymbolAddress((void**)&prpA,   g_rpA);
    cudaGetSymbolAddress((void**)&prpP,   g_rpP);
    cudaGetSymbolAddress((void**)&poffA,  g_offA);
    cudaGetSymbolAddress((void**)&poffP,  g_offP);
    cudaGetSymbolAddress((void**)&pbA,    g_bsumA);
    cudaGetSymbolAddress((void**)&pbP,    g_bsumP);
    cudaGetSymbolAddress((void**)&pecvA,  g_ecvA);
    cudaGetSymbolAddress((void**)&pecvP,  g_ecvP);

    const int nbA = (N_A + 2047) / 2048;
    const int nbP = (N_P + 2047) / 2048;
    const int ngA = (N_A + 255) / 256;
    const int ngP = (N_P + 255) / 256;
    const int gT  = (int)(((size_t)N_TOT * 32 + 255) / 256);
    const int Emax = E1 > E2 ? E1 : E2;

    // one-time resources (identical work on every call; just host objects)
    static cudaStream_t s2 = nullptr;
    static cudaEvent_t evFork = nullptr, evCsr = nullptr;
    if (s2 == nullptr) {
        cudaStreamCreateWithFlags(&s2, cudaStreamNonBlocking);
        cudaEventCreateWithFlags(&evFork, cudaEventDisableTiming);
        cudaEventCreateWithFlags(&evCsr,  cudaEventDisableTiming);
    }
    cudaFuncSetAttribute(proj_norm_wmma_kernel,
                         cudaFuncAttributeMaxDynamicSharedMemorySize, PROJ_SMEM);

    // fork: CSR build on s2 runs concurrently with wcomb+projection on main
    cudaEventRecord(evFork, 0);
    cudaStreamWaitEvent(s2, evFork, 0);

    // main stream: weight pre-combine + tensor-core projection
    wcomb2_kernel<<<2 * D, D>>>(Wp0, Wp1, W1, pW0c, pW1c);
    proj_norm_wmma_kernel<<<(N_A + 63) / 64 + (N_P + 63) / 64, 256, PROJ_SMEM>>>(
        x0, x1, pW0c, pW1c, b1, px16);

    // s2: CSR build (independent of projection)
    hist2_kernel<<<(Emax + 255) / 256, 256, 0, s2>>>(rows_ap, E1, pcntA, rows_pa, E2, pcntP);
    scan1_kernel<<<nbA + nbP, 256, 0, s2>>>(pcntA, N_A, prpA, pbA, nbA, pcntP, N_P, prpP, pbP);
    scan2_kernel<<<2, 256, 0, s2>>>(pbA, nbA, pbP, nbP);
    scan3_kernel<<<ngA + ngP, 256, 0, s2>>>(pbA, N_A, prpA, poffA, pcntA, ngA,
                                            pbP, N_P, prpP, poffP, pcntP);
    scatter2_kernel<<<(Emax + 255) / 256, 256, 0, s2>>>(
        rows_ap, cols_ap, vals_ap, E1, poffA, pecvA, pcntA,
        rows_pa, cols_pa, vals_pa, E2, poffP, pecvP, pcntP);
    cudaEventRecord(evCsr, s2);

    // join: SpMM phase needs both projection (main) and CSR (s2)
    cudaStreamWaitEvent(0, evCsr, 0);

    // ---------------- pass 1 (first_order = AP, PA) ----------------
    spmm_hop1_kernel<<<gT, 256>>>(prpA, pecvA, px16 + (size_t)N_A * 32, phA16, phA8,
                                  prpP, pecvP, px16,                    phP16, phP8);
    spmm_fused_kernel<<<gT, 256>>>(prpA, pecvA, prpP, pecvP,
                                   phA16, phP16, phA8, phP8,
                                   px16, pres16, coe);

    // ---------------- pass 2 (first_order = PA, AP) ----------------
    spmm_hop1_kernel<<<gT, 256>>>(prpA, pecvA, pres16 + (size_t)N_A * 32, phA16, phA8,
                                  prpP, pecvP, pres16,                    phP16, phP8);
    spmm_fused_out_kernel<<<gT, 256>>>(prpA, pecvA, prpP, pecvP,
                                       phA16, phP16, phA8, phP8,
                                       pres16, out, coe, W2, b2);
}

// round 16
// speedup vs baseline: 2.2935x; 1.7987x over previous
#include <cuda_runtime.h>
#include <cuda_fp16.h>
#include <mma.h>
#include <cstddef>
#include <cstdint>

using namespace nvcuda;

#define N_A   100000
#define N_P   150000
#define N_TOT (N_A + N_P)
#define D     128
#define C_OUT 16
#define EMAX  2000000

// -------------------- device scratch (no allocs allowed) --------------------
// 16-dim planes (64B per row, fp32) — the whole pipeline runs here post-proj.
__device__ float g_yx [(size_t)N_TOT * C_OUT];  // z @ W2
__device__ float g_y1 [(size_t)N_TOT * C_OUT];  // res1 @ W2
__device__ float g_yhA[(size_t)N_A  * C_OUT];   // hop-1 outputs (A rows)
__device__ float g_yhP[(size_t)N_P  * C_OUT];
__device__ float g_W0c [D * D];
__device__ float g_W1c [D * D];
// CSR scratch (cnt zeroed by scatter2 each run; zero-init covers run #1)
__device__ int   g_cntA[N_A],     g_cntP[N_P];
__device__ int   g_rpA [N_A + 1], g_rpP [N_P + 1];
__device__ int   g_offA[N_A],     g_offP[N_P];
__device__ int   g_bsumA[256],    g_bsumP[256];
__device__ __align__(16) uint2 g_ecvA[EMAX];    // (col_local, val bits)
__device__ __align__(16) uint2 g_ecvP[EMAX];

// ------------------- 16-dim gather: quarter-warp per edge -------------------
// lane = grp*4 + q : group grp (0..7) handles edge i+grp, lane loads float4 q
// of the 16-float row. 8 edges in flight per instruction. xor-reduce over grp.
__device__ __forceinline__ float4 gather_y(
    const uint2* __restrict__ ecv, const float4* __restrict__ y,
    int s, int e, int grp, int q) {
    float4 acc = {0.f, 0.f, 0.f, 0.f};
    for (int i = s; i < e; i += 8) {
        int idx = i + grp;
        bool valid = idx < e;
        uint2 p = __ldg(&ecv[valid ? idx : s]);
        float v = valid ? __uint_as_float(p.y) : 0.f;
        float4 h = __ldg(y + (size_t)p.x * 4 + q);
        acc.x += v * h.x; acc.y += v * h.y; acc.z += v * h.z; acc.w += v * h.w;
    }
    #pragma unroll
    for (int o = 4; o < 32; o <<= 1) {
        acc.x += __shfl_xor_sync(0xffffffffu, acc.x, o);
        acc.y += __shfl_xor_sync(0xffffffffu, acc.y, o);
        acc.z += __shfl_xor_sync(0xffffffffu, acc.z, o);
        acc.w += __shfl_xor_sync(0xffffffffu, acc.w, o);
    }
    return acc;   // lanes sharing q hold the final sum; lanes 0-3 cover the row
}

// -------------------- Wc = Wp @ W1 (both weights, one launch) ----------------
__global__ void __launch_bounds__(128) wcomb2_kernel(
    const float* __restrict__ Wp0, const float* __restrict__ Wp1,
    const float* __restrict__ W1,
    float* __restrict__ Wc0, float* __restrict__ Wc1) {
    __shared__ float srow[D];
    const float* Wp = (blockIdx.x < 128) ? Wp0 : Wp1;
    float*       Wc = (blockIdx.x < 128) ? Wc0 : Wc1;
    int r = blockIdx.x & 127;
    srow[threadIdx.x] = Wp[r * D + threadIdx.x];
    __syncthreads();
    float acc = 0.f;
    #pragma unroll 8
    for (int k = 0; k < D; k++)
        acc += srow[k] * __ldg(&W1[k * D + threadIdx.x]);
    Wc[r * D + threadIdx.x] = acc;
}

// - tensor-core projection: z = rownorm(relu(x@Wc+b)); writes y_x = z@W2 only -
#define LDX 144
#define LDO 136
#define PROJ_SMEM (64 * LDX * 2 + 128 * LDX * 2)
__global__ void __launch_bounds__(256) proj_norm_wmma_kernel(
    const float* __restrict__ x0, const float* __restrict__ x1,
    const float* __restrict__ Wc0, const float* __restrict__ Wc1,
    const float* __restrict__ bias, const float* __restrict__ W2,
    float* __restrict__ yx) {
    extern __shared__ char smem[];
    __half* sX = (__half*)smem;                       // [64][LDX]
    __half* sW = (__half*)(smem + 64 * LDX * 2);      // [128][LDX]
    float*  sO = (float*)(smem + 64 * LDX * 2);       // [64][LDO], reuses sW
    __shared__ float sW2[C_OUT][D];                   // class-major W2

    const int nblkA = (N_A + 63) / 64;
    const float* xin;
    const float* Wc;
    int row0, nrows, base_out;
    if ((int)blockIdx.x < nblkA) {
        xin = x0; Wc = Wc0; row0 = blockIdx.x * 64; nrows = N_A; base_out = 0;
    } else {
        xin = x1; Wc = Wc1; row0 = (blockIdx.x - nblkA) * 64; nrows = N_P; base_out = N_A;
    }
    const int tid = threadIdx.x;

    for (int i = tid; i < C_OUT * D; i += 256) {
        int c = i >> 7, k = i & 127;
        sW2[c][k] = __ldg(&W2[k * C_OUT + c]);
    }
    for (int idx = tid; idx < 64 * 128; idx += 256) {
        int r = idx >> 7, c = idx & 127;
        float v = (row0 + r < nrows) ? __ldg(&xin[(size_t)(row0 + r) * D + c]) : 0.f;
        sX[r * LDX + c] = __float2half(v);
    }
    for (int idx = tid; idx < 128 * 128; idx += 256) {
        int k = idx >> 7, n = idx & 127;
        sW[k * LDX + n] = __float2half(__ldg(&Wc[idx]));
    }
    __syncthreads();

    const int warp = tid >> 5;
    const int wm = warp >> 1, wn = warp & 1;
    wmma::fragment<wmma::accumulator, 16, 16, 16, float> acc[4];
    #pragma unroll
    for (int j = 0; j < 4; j++) wmma::fill_fragment(acc[j], 0.f);
    #pragma unroll
    for (int k0 = 0; k0 < 8; k0++) {
        wmma::fragment<wmma::matrix_a, 16, 16, 16, __half, wmma::row_major> a;
        wmma::load_matrix_sync(a, sX + wm * 16 * LDX + k0 * 16, LDX);
        #pragma unroll
        for (int j = 0; j < 4; j++) {
            wmma::fragment<wmma::matrix_b, 16, 16, 16, __half, wmma::row_major> b;
            wmma::load_matrix_sync(b, sW + k0 * 16 * LDX + wn * 64 + j * 16, LDX);
            wmma::mma_sync(acc[j], a, b, acc[j]);
        }
    }
    __syncthreads();
    #pragma unroll
    for (int j = 0; j < 4; j++)
        wmma::store_matrix_sync(sO + wm * 16 * LDO + wn * 64 + j * 16, acc[j],
                                LDO, wmma::mem_row_major);
    __syncthreads();

    // epilogue: bias+relu+rownorm, then y_x = z @ W2 (per-row shuffle reduce)
    const int lane = tid & 31;
    float4 bv = __ldg((const float4*)bias + lane);
    #pragma unroll
    for (int i = 0; i < 8; i++) {
        int row = warp * 8 + i;
        float4 v = *(const float4*)&sO[row * LDO + lane * 4];
        v.x += bv.x; v.y += bv.y; v.z += bv.z; v.w += bv.w;
        v.x = v.x > 0.f ? v.x : 0.f;
        v.y = v.y > 0.f ? v.y : 0.f;
        v.z = v.z > 0.f ? v.z : 0.f;
        v.w = v.w > 0.f ? v.w : 0.f;
        float s = v.x + v.y + v.z + v.w;
        float q = v.x * v.x + v.y * v.y + v.z * v.z + v.w * v.w;
        #pragma unroll
        for (int o = 16; o; o >>= 1) {
            s += __shfl_xor_sync(0xffffffffu, s, o);
            q += __shfl_xor_sync(0xffffffffu, q, o);
        }
        float mean = s * (1.f / 128.f);
        float var  = (q - 128.f * mean * mean) * (1.f / 127.f);
        float rstd = (var > 0.f) ? rsqrtf(var) : 0.f;
        float z0 = (v.x - mean) * rstd;
        float z1 = (v.y - mean) * rstd;
        float z2 = (v.z - mean) * rstd;
        float z3 = (v.w - mean) * rstd;

        float p[C_OUT];
        #pragma unroll
        for (int c = 0; c < C_OUT; c++) {
            float4 wv = *(const float4*)&sW2[c][lane * 4];
            p[c] = z0 * wv.x + z1 * wv.y + z2 * wv.z + z3 * wv.w;
        }
        #pragma unroll
        for (int off = 16; off; off >>= 1) {
            #pragma unroll
            for (int c = 0; c < C_OUT; c++)
                p[c] += __shfl_xor_sync(0xffffffffu, p[c], off);
        }
        int r = row0 + row;
        if (lane < C_OUT && r < nrows)
            yx[(size_t)(base_out + r) * C_OUT + lane] = p[lane];
    }
}

// ------------------------------ CSR build -----------------------------------
__global__ void __launch_bounds__(256) hist2_kernel(
    const int* __restrict__ rowsA, int E1, int* __restrict__ cntA,
    const int* __restrict__ rowsP, int E2, int* __restrict__ cntP) {
    int i = blockIdx.x * 256 + threadIdx.x;
    if (i < E1) atomicAdd(&cntA[__ldg(&rowsA[i])], 1);
    if (i < E2) atomicAdd(&cntP[__ldg(&rowsP[i]) - N_A], 1);
}

__global__ void __launch_bounds__(256) scan1_kernel(
    const int* __restrict__ cntA, int nA, int* __restrict__ rpA, int* __restrict__ bsumA, int nbA,
    const int* __restrict__ cntP, int nP, int* __restrict__ rpP, int* __restrict__ bsumP) {
    __shared__ int wsum[8];
    const int* cnt; int n; int* rp; int* bsum; int blk;
    if ((int)blockIdx.x < nbA) { cnt = cntA; n = nA; rp = rpA; bsum = bsumA; blk = blockIdx.x; }
    else                       { cnt = cntP; n = nP; rp = rpP; bsum = bsumP; blk = blockIdx.x - nbA; }
    const int base = blk * 2048;
    const int t = threadIdx.x;
    int v[8]; int s = 0;
    #pragma unroll
    for (int i = 0; i < 8; i++) {
        int idx = base + t * 8 + i;
        int c = (idx < n) ? __ldg(&cnt[idx]) : 0;
        v[i] = s; s += c;
    }
    int lane = t & 31, w = t >> 5;
    int p = s;
    #pragma unroll
    for (int o = 1; o < 32; o <<= 1) {
        int q = __shfl_up_sync(0xffffffffu, p, o);
        if (lane >= o) p += q;
    }
    if (lane == 31) wsum[w] = p;
    __syncthreads();
    if (t < 8) {
        int ws = wsum[t];
        int pp = ws;
        #pragma unroll
        for (int o = 1; o < 8; o <<= 1) {
            int q = __shfl_up_sync(0xffu, pp, o);
            if (t >= o) pp += q;
        }
        wsum[t] = pp - ws;
        if (t == 7) bsum[blk] = pp;
    }
    __syncthreads();
    int texcl = (p - s) + wsum[w];
    #pragma unroll
    for (int i = 0; i < 8; i++) {
        int idx = base + t * 8 + i;
        if (idx < n) rp[idx] = texcl + v[i];
    }
}

__global__ void __launch_bounds__(256) scan2_kernel(
    int* __restrict__ bsumA, int nbA, int* __restrict__ bsumP, int nbP) {
    __shared__ int sh[256];
    int* bsum = blockIdx.x == 0 ? bsumA : bsumP;
    int nb    = blockIdx.x == 0 ? nbA   : nbP;
    int t = threadIdx.x;
    int v = (t < nb) ? bsum[t] : 0;
    sh[t] = v; __syncthreads();
    #pragma unroll
    for (int o = 1; o < 256; o <<= 1) {
        int q = (t >= o) ? sh[t - o] : 0;
        __syncthreads();
        sh[t] += q;
        __syncthreads();
    }
    if (t < nb) bsum[t] = sh[t] - v;
}

__global__ void __launch_bounds__(256) scan3_kernel(
    const int* __restrict__ bsumA, int nA, int* __restrict__ rpA, int* __restrict__ offsA,
    const int* __restrict__ cntA, int ngA,
    const int* __restrict__ bsumP, int nP, int* __restrict__ rpP, int* __restrict__ offsP,
    const int* __restrict__ cntP) {
    const int* bsum; int n; int* rp; int* offs; const int* cnt; int idx;
    if ((int)blockIdx.x < ngA) {
        bsum = bsumA; n = nA; rp = rpA; offs = offsA; cnt = cntA;
        idx = blockIdx.x * 256 + threadIdx.x;
    } else {
        bsum = bsumP; n = nP; rp = rpP; offs = offsP; cnt = cntP;
        idx = (blockIdx.x - ngA) * 256 + threadIdx.x;
    }
    if (idx < n) {
        int v = rp[idx] + __ldg(&bsum[idx >> 11]);
        rp[idx] = v;
        offs[idx] = v;
        if (idx == n - 1) rp[n] = v + __ldg(&cnt[idx]);
    }
}

__global__ void __launch_bounds__(256) scatter2_kernel(
    const int* __restrict__ rowsA, const int* __restrict__ colsA,
    const float* __restrict__ valsA, int E1, int* __restrict__ offsA, uint2* __restrict__ ecvA,
    int* __restrict__ cntA,
    const int* __restrict__ rowsP, const int* __restrict__ colsP,
    const float* __restrict__ valsP, int E2, int* __restrict__ offsP, uint2* __restrict__ ecvP,
    int* __restrict__ cntP) {
    int i = blockIdx.x * 256 + threadIdx.x;
    if (i < N_A) cntA[i] = 0;
    if (i < N_P) cntP[i] = 0;
    if (i < E1) {
        int r = __ldg(&rowsA[i]);
        int pos = atomicAdd(&offsA[r], 1);
        ecvA[pos] = make_uint2((unsigned)(__ldg(&colsA[i]) - N_A), __float_as_uint(__ldg(&valsA[i])));
    }
    if (i < E2) {
        int r = __ldg(&rowsP[i]) - N_A;
        int pos = atomicAdd(&offsP[r], 1);
        ecvP[pos] = make_uint2((unsigned)__ldg(&colsP[i]), __float_as_uint(__ldg(&valsP[i])));
    }
}

// ---------------- 16-dim hop-1 SpMM (A + P in one grid) ----------------------
__global__ void __launch_bounds__(256) spmm_hop1_y_kernel(
    const int* __restrict__ rpA, const uint2* __restrict__ ecvA,
    const float4* __restrict__ srcA, float4* __restrict__ dstA,
    const int* __restrict__ rpP, const uint2* __restrict__ ecvP,
    const float4* __restrict__ srcP, float4* __restrict__ dstP) {
    int g = (int)((blockIdx.x * 256u + threadIdx.x) >> 5);
    if (g >= N_TOT) return;
    int lane = threadIdx.x & 31, grp = lane >> 2, q = lane & 3;
    const int* rp; const uint2* ecv; const float4* src; float4* dst; int r;
    if (g < N_A) { rp = rpA; ecv = ecvA; src = srcA; dst = dstA; r = g; }
    else         { rp = rpP; ecv = ecvP; src = srcP; dst = dstP; r = g - N_A; }
    int s = __ldg(&rp[r]), e = __ldg(&rp[r + 1]);
    float4 a = gather_y(ecv, src, s, e, grp, q);
    if (grp == 0) dst[(size_t)r * 4 + q] = a;
}

// ---------- 16-dim hop-2 fused with combine (pass 1: -> y1) ------------------
__global__ void __launch_bounds__(256) spmm_fused_y_kernel(
    const int* __restrict__ rpA, const uint2* __restrict__ ecvA,
    const int* __restrict__ rpP, const uint2* __restrict__ ecvP,
    const float4* __restrict__ yhA, const float4* __restrict__ yhP,
    const float4* __restrict__ yx, float4* __restrict__ y1,
    const float* __restrict__ coe) {
    int g = (int)((blockIdx.x * 256u + threadIdx.x) >> 5);
    if (g >= N_TOT) return;
    int lane = threadIdx.x & 31, grp = lane >> 2, q = lane & 3;
    const int* rp; const uint2* ecv; const float4* yh_src; const float4* yh_own;
    int r, c_own, c_hop;
    if (g < N_A) { rp = rpA; ecv = ecvA; yh_src = yhP; yh_own = yhA; r = g;       c_own = 1; c_hop = 3; }
    else         { rp = rpP; ecv = ecvP; yh_src = yhA; yh_own = yhP; r = g - N_A; c_own = 2; c_hop = 4; }
    int s = __ldg(&rp[r]), e = __ldg(&rp[r + 1]);
    float4 w = gather_y(ecv, yh_src, s, e, grp, q);
    if (grp == 0) {
        size_t R = (size_t)g;
        float c0 = __ldg(&coe[0]);
        float cw = __ldg(&coe[c_own]);
        float ch = __ldg(&coe[c_hop]);
        float4 xv = __ldg(yx + R * 4 + q);
        float4 hv = __ldg(yh_own + (size_t)r * 4 + q);
        float4 o;
        o.x = c0 * xv.x + cw * hv.x + ch * w.x;
        o.y = c0 * xv.y + cw * hv.y + ch * w.y;
        o.z = c0 * xv.z + cw * hv.z + ch * w.z;
        o.w = c0 * xv.w + cw * hv.w + ch * w.w;
        y1[R * 4 + q] = o;
    }
}

// ----- 16-dim hop-2 fused with combine + bias (pass 2: -> out) ---------------
__global__ void __launch_bounds__(256) spmm_fused_out_y_kernel(
    const int* __restrict__ rpA, const uint2* __restrict__ ecvA,
    const int* __restrict__ rpP, const uint2* __restrict__ ecvP,
    const float4* __restrict__ yhA, const float4* __restrict__ yhP,
    const float4* __restrict__ y1, float4* __restrict__ out,
    const float* __restrict__ coe, const float* __restrict__ b2) {
    int g = (int)((blockIdx.x * 256u + threadIdx.x) >> 5);
    if (g >= N_TOT) return;
    int lane = threadIdx.x & 31, grp = lane >> 2, q = lane & 3;
    const int* rp; const uint2* ecv; const float4* yh_src; const float4* yh_own;
    int r, c_own, c_hop;
    if (g < N_A) { rp = rpA; ecv = ecvA; yh_src = yhP; yh_own = yhA; r = g;       c_own = 2; c_hop = 4; }
    else         { rp = rpP; ecv = ecvP; yh_src = yhA; yh_own = yhP; r = g - N_A; c_own = 1; c_hop = 3; }
    int s = __ldg(&rp[r]), e = __ldg(&rp[r + 1]);
    float4 w = gather_y(ecv, yh_src, s, e, grp, q);
    if (grp == 0) {
        size_t R = (size_t)g;
        float c0 = __ldg(&coe[0]);
        float cw = __ldg(&coe[c_own]);
        float ch = __ldg(&coe[c_hop]);
        float4 xv = __ldg(y1 + R * 4 + q);
        float4 hv = __ldg(yh_own + (size_t)r * 4 + q);
        float4 bb = __ldg((const float4*)b2 + q);
        float4 o;
        o.x = c0 * xv.x + cw * hv.x + ch * w.x + bb.x;
        o.y = c0 * xv.y + cw * hv.y + ch * w.y + bb.y;
        o.z = c0 * xv.z + cw * hv.z + ch * w.z + bb.z;
        o.w = c0 * xv.w + cw * hv.w + ch * w.w + bb.w;
        out[R * 4 + q] = o;
    }
}

// ----------------------------------- launch ---------------------------------
extern "C" void kernel_launch(void* const* d_in, const int* in_sizes, int n_in,
                              void* d_out, int out_size) {
    const float* x0      = (const float*)d_in[0];
    const float* x1      = (const float*)d_in[1];
    const float* vals_ap = (const float*)d_in[2];
    const float* vals_pa = (const float*)d_in[3];
    const int*   rows_ap = (const int*)  d_in[4];
    const int*   cols_ap = (const int*)  d_in[5];
    const int*   rows_pa = (const int*)  d_in[6];
    const int*   cols_pa = (const int*)  d_in[7];
    const float* Wp0     = (const float*)d_in[8];
    const float* Wp1     = (const float*)d_in[9];
    const float* W1      = (const float*)d_in[10];
    const float* b1      = (const float*)d_in[11];
    const float* W2      = (const float*)d_in[12];
    const float* b2      = (const float*)d_in[13];
    const float* coe     = (const float*)d_in[14];
    float* out = (float*)d_out;

    const int E1 = in_sizes[2];
    const int E2 = in_sizes[3];

    float *pW0c, *pW1c, *pyx, *py1, *pyhA, *pyhP;
    uint2 *pecvA, *pecvP;
    int *pcntA, *pcntP, *prpA, *prpP, *poffA, *poffP, *pbA, *pbP;
    cudaGetSymbolAddress((void**)&pyx,   g_yx);
    cudaGetSymbolAddress((void**)&py1,   g_y1);
    cudaGetSymbolAddress((void**)&pyhA,  g_yhA);
    cudaGetSymbolAddress((void**)&pyhP,  g_yhP);
    cudaGetSymbolAddress((void**)&pW0c,  g_W0c);
    cudaGetSymbolAddress((void**)&pW1c,  g_W1c);
    cudaGetSymbolAddress((void**)&pcntA, g_cntA);
    cudaGetSymbolAddress((void**)&pcntP, g_cntP);
    cudaGetSymbolAddress((void**)&prpA,  g_rpA);
    cudaGetSymbolAddress((void**)&prpP,  g_rpP);
    cudaGetSymbolAddress((void**)&poffA, g_offA);
    cudaGetSymbolAddress((void**)&poffP, g_offP);
    cudaGetSymbolAddress((void**)&pbA,   g_bsumA);
    cudaGetSymbolAddress((void**)&pbP,   g_bsumP);
    cudaGetSymbolAddress((void**)&pecvA, g_ecvA);
    cudaGetSymbolAddress((void**)&pecvP, g_ecvP);

    const int nbA = (N_A + 2047) / 2048;
    const int nbP = (N_P + 2047) / 2048;
    const int ngA = (N_A + 255) / 256;
    const int ngP = (N_P + 255) / 256;
    const int gT  = (int)(((size_t)N_TOT * 32 + 255) / 256);
    const int Emax = E1 > E2 ? E1 : E2;

    // one-time host resources
    static cudaStream_t s2 = nullptr;
    static cudaEvent_t evFork = nullptr, evCsr = nullptr;
    if (s2 == nullptr) {
        cudaStreamCreateWithFlags(&s2, cudaStreamNonBlocking);
        cudaEventCreateWithFlags(&evFork, cudaEventDisableTiming);
        cudaEventCreateWithFlags(&evCsr,  cudaEventDisableTiming);
    }
    cudaFuncSetAttribute(proj_norm_wmma_kernel,
                         cudaFuncAttributeMaxDynamicSharedMemorySize, PROJ_SMEM);

    // fork: CSR build on s2 concurrent with wcomb+projection on main
    cudaEventRecord(evFork, 0);
    cudaStreamWaitEvent(s2, evFork, 0);

    wcomb2_kernel<<<2 * D, D>>>(Wp0, Wp1, W1, pW0c, pW1c);
    proj_norm_wmma_kernel<<<(N_A + 63) / 64 + (N_P + 63) / 64, 256, PROJ_SMEM>>>(
        x0, x1, pW0c, pW1c, b1, W2, pyx);

    hist2_kernel<<<(Emax + 255) / 256, 256, 0, s2>>>(rows_ap, E1, pcntA, rows_pa, E2, pcntP);
    scan1_kernel<<<nbA + nbP, 256, 0, s2>>>(pcntA, N_A, prpA, pbA, nbA, pcntP, N_P, prpP, pbP);
    scan2_kernel<<<2, 256, 0, s2>>>(pbA, nbA, pbP, nbP);
    scan3_kernel<<<ngA + ngP, 256, 0, s2>>>(pbA, N_A, prpA, poffA, pcntA, ngA,
                                            pbP, N_P, prpP, poffP, pcntP);
    scatter2_kernel<<<(Emax + 255) / 256, 256, 0, s2>>>(
        rows_ap, cols_ap, vals_ap, E1, poffA, pecvA, pcntA,
        rows_pa, cols_pa, vals_pa, E2, poffP, pecvP, pcntP);
    cudaEventRecord(evCsr, s2);
    cudaStreamWaitEvent(0, evCsr, 0);

    // ---------------- pass 1 (first_order = AP, PA), all 16-dim --------------
    spmm_hop1_y_kernel<<<gT, 256>>>(prpA, pecvA, (const float4*)(pyx + (size_t)N_A * C_OUT),
                                    (float4*)pyhA,
                                    prpP, pecvP, (const float4*)pyx, (float4*)pyhP);
    spmm_fused_y_kernel<<<gT, 256>>>(prpA, pecvA, prpP, pecvP,
                                     (const float4*)pyhA, (const float4*)pyhP,
                                     (const float4*)pyx, (float4*)py1, coe);

    // ---------------- pass 2 (first_order = PA, AP), all 16-dim --------------
    spmm_hop1_y_kernel<<<gT, 256>>>(prpA, pecvA, (const float4*)(py1 + (size_t)N_A * C_OUT),
                                    (float4*)pyhA,
                                    prpP, pecvP, (const float4*)py1, (float4*)pyhP);
    spmm_fused_out_y_kernel<<<gT, 256>>>(prpA, pecvA, prpP, pecvP,
                                         (const float4*)pyhA, (const float4*)pyhP,
                                         (const float4*)py1, (float4*)out, coe, b2);
}

// round 17
// speedup vs baseline: 2.5783x; 1.1242x over previous
#include <cuda_runtime.h>
#include <cuda_fp16.h>
#include <mma.h>
#include <cstddef>
#include <cstdint>

using namespace nvcuda;

#define N_A   100000
#define N_P   150000
#define N_TOT (N_A + N_P)
#define D     128
#define C_OUT 16
#define EMAX  2000000

// -------------------- device scratch (no allocs allowed) --------------------
__device__ float g_yx [(size_t)N_TOT * C_OUT];  // z @ W2
__device__ float g_y1 [(size_t)N_TOT * C_OUT];  // res1 @ W2
__device__ float g_yhA[(size_t)N_A  * C_OUT];   // hop-1 outputs (A rows)
__device__ float g_yhP[(size_t)N_P  * C_OUT];
__device__ float g_W0c [D * D];
__device__ float g_W1c [D * D];
// CSR scratch (cnt zeroed by scatter2 each run; zero-init covers run #1)
__device__ int   g_cntA[N_A],     g_cntP[N_P];
__device__ int   g_rpA [N_A + 1], g_rpP [N_P + 1];
__device__ int   g_offA[N_A],     g_offP[N_P];
__device__ int   g_bsumA[256],    g_bsumP[256];
__device__ __align__(16) uint2 g_ecvA[EMAX];    // (col_local, val bits)
__device__ __align__(16) uint2 g_ecvP[EMAX];

// ------------------- 16-dim gather: quarter-warp per edge -------------------
// lane = grp*4 + q. Group grp handles edge i+grp; lane loads float4 q of the
// 16-float row. 8 edges in flight per iteration; next ecv prefetched so the
// ecv->gather chain doesn't serialize. xor-reduce over groups at the end.
__device__ __forceinline__ float4 gather_y(
    const uint2* __restrict__ ecv, const float4* __restrict__ y,
    int s, int e, int grp, int q) {
    float4 acc = {0.f, 0.f, 0.f, 0.f};
    int i = s;
    if (i < e) {
        int idx = i + grp;
        bool val = idx < e;
        uint2 p = __ldg(&ecv[val ? idx : s]);
        for (; i + 8 < e; i += 8) {
            int nidx = i + 8 + grp;
            bool nval = nidx < e;
            uint2 np = __ldg(&ecv[nval ? nidx : s]);   // prefetch next
            float v = val ? __uint_as_float(p.y) : 0.f;
            float4 h = __ldg(y + (size_t)p.x * 4 + q);
            acc.x += v * h.x; acc.y += v * h.y; acc.z += v * h.z; acc.w += v * h.w;
            p = np; val = nval;
        }
        float v = val ? __uint_as_float(p.y) : 0.f;
        float4 h = __ldg(y + (size_t)p.x * 4 + q);
        acc.x += v * h.x; acc.y += v * h.y; acc.z += v * h.z; acc.w += v * h.w;
    }
    #pragma unroll
    for (int o = 4; o < 32; o <<= 1) {
        acc.x += __shfl_xor_sync(0xffffffffu, acc.x, o);
        acc.y += __shfl_xor_sync(0xffffffffu, acc.y, o);
        acc.z += __shfl_xor_sync(0xffffffffu, acc.z, o);
        acc.w += __shfl_xor_sync(0xffffffffu, acc.w, o);
    }
    return acc;
}

// -------------------- Wc = Wp @ W1 (both weights, one launch) ----------------
__global__ void __launch_bounds__(128) wcomb2_kernel(
    const float* __restrict__ Wp0, const float* __restrict__ Wp1,
    const float* __restrict__ W1,
    float* __restrict__ Wc0, float* __restrict__ Wc1) {
    __shared__ float srow[D];
    const float* Wp = (blockIdx.x < 128) ? Wp0 : Wp1;
    float*       Wc = (blockIdx.x < 128) ? Wc0 : Wc1;
    int r = blockIdx.x & 127;
    srow[threadIdx.x] = Wp[r * D + threadIdx.x];
    __syncthreads();
    float acc = 0.f;
    #pragma unroll 8
    for (int k = 0; k < D; k++)
        acc += srow[k] * __ldg(&W1[k * D + threadIdx.x]);
    Wc[r * D + threadIdx.x] = acc;
}

// - tensor-core projection: z = rownorm(relu(x@Wc+b)); writes y_x = z@W2 only -
#define LDX 144
#define LDO 136
#define PROJ_SMEM (64 * LDX * 2 + 128 * LDX * 2)
__global__ void __launch_bounds__(256) proj_norm_wmma_kernel(
    const float* __restrict__ x0, const float* __restrict__ x1,
    const float* __restrict__ Wc0, const float* __restrict__ Wc1,
    const float* __restrict__ bias, const float* __restrict__ W2,
    float* __restrict__ yx) {
    extern __shared__ char smem[];
    __half* sX = (__half*)smem;                       // [64][LDX]
    __half* sW = (__half*)(smem + 64 * LDX * 2);      // [128][LDX]
    float*  sO = (float*)(smem + 64 * LDX * 2);       // [64][LDO], reuses sW
    __shared__ float sW2[C_OUT][D];                   // class-major W2

    const int nblkA = (N_A + 63) / 64;
    const float* xin;
    const float* Wc;
    int row0, nrows, base_out;
    if ((int)blockIdx.x < nblkA) {
        xin = x0; Wc = Wc0; row0 = blockIdx.x * 64; nrows = N_A; base_out = 0;
    } else {
        xin = x1; Wc = Wc1; row0 = (blockIdx.x - nblkA) * 64; nrows = N_P; base_out = N_A;
    }
    const int tid = threadIdx.x;

    for (int i = tid; i < C_OUT * D; i += 256) {
        int c = i >> 7, k = i & 127;
        sW2[c][k] = __ldg(&W2[k * C_OUT + c]);
    }
    // vectorized fp32->fp16 staging of x tile (float4 = 4 elems per load)
    #pragma unroll
    for (int i = 0; i < 8; i++) {
        int idx = tid + i * 256;          // float4 index, 0..2047
        int r = idx >> 5, c4 = idx & 31;
        float4 v = make_float4(0.f, 0.f, 0.f, 0.f);
        if (row0 + r < nrows)
            v = __ldg((const float4*)(xin + (size_t)(row0 + r) * D) + c4);
        __half* d = sX + r * LDX + c4 * 4;
        d[0] = __float2half(v.x); d[1] = __float2half(v.y);
        d[2] = __float2half(v.z); d[3] = __float2half(v.w);
    }
    // vectorized staging of Wc
    #pragma unroll
    for (int i = 0; i < 16; i++) {
        int idx = tid + i * 256;          // float4 index, 0..4095
        int k = idx >> 5, c4 = idx & 31;
        float4 v = __ldg((const float4*)Wc + idx);
        __half* d = sW + k * LDX + c4 * 4;
        d[0] = __float2half(v.x); d[1] = __float2half(v.y);
        d[2] = __float2half(v.z); d[3] = __float2half(v.w);
    }
    __syncthreads();

    const int warp = tid >> 5;
    const int wm = warp >> 1, wn = warp & 1;
    wmma::fragment<wmma::accumulator, 16, 16, 16, float> acc[4];
    #pragma unroll
    for (int j = 0; j < 4; j++) wmma::fill_fragment(acc[j], 0.f);
    #pragma unroll
    for (int k0 = 0; k0 < 8; k0++) {
        wmma::fragment<wmma::matrix_a, 16, 16, 16, __half, wmma::row_major> a;
        wmma::load_matrix_sync(a, sX + wm * 16 * LDX + k0 * 16, LDX);
        #pragma unroll
        for (int j = 0; j < 4; j++) {
            wmma::fragment<wmma::matrix_b, 16, 16, 16, __half, wmma::row_major> b;
            wmma::load_matrix_sync(b, sW + k0 * 16 * LDX + wn * 64 + j * 16, LDX);
            wmma::mma_sync(acc[j], a, b, acc[j]);
        }
    }
    __syncthreads();
    #pragma unroll
    for (int j = 0; j < 4; j++)
        wmma::store_matrix_sync(sO + wm * 16 * LDO + wn * 64 + j * 16, acc[j],
                                LDO, wmma::mem_row_major);
    __syncthreads();

    // epilogue: bias+relu+rownorm, then y_x = z @ W2 (per-row shuffle reduce)
    const int lane = tid & 31;
    float4 bv = __ldg((const float4*)bias + lane);
    #pragma unroll
    for (int i = 0; i < 8; i++) {
        int row = warp * 8 + i;
        float4 v = *(const float4*)&sO[row * LDO + lane * 4];
        v.x += bv.x; v.y += bv.y; v.z += bv.z; v.w += bv.w;
        v.x = v.x > 0.f ? v.x : 0.f;
        v.y = v.y > 0.f ? v.y : 0.f;
        v.z = v.z > 0.f ? v.z : 0.f;
        v.w = v.w > 0.f ? v.w : 0.f;
        float s = v.x + v.y + v.z + v.w;
        float q = v.x * v.x + v.y * v.y + v.z * v.z + v.w * v.w;
        #pragma unroll
        for (int o = 16; o; o >>= 1) {
            s += __shfl_xor_sync(0xffffffffu, s, o);
            q += __shfl_xor_sync(0xffffffffu, q, o);
        }
        float mean = s * (1.f / 128.f);
        float var  = (q - 128.f * mean * mean) * (1.f / 127.f);
        float rstd = (var > 0.f) ? rsqrtf(var) : 0.f;
        float z0 = (v.x - mean) * rstd;
        float z1 = (v.y - mean) * rstd;
        float z2 = (v.z - mean) * rstd;
        float z3 = (v.w - mean) * rstd;

        float p[C_OUT];
        #pragma unroll
        for (int c = 0; c < C_OUT; c++) {
            float4 wv = *(const float4*)&sW2[c][lane * 4];
            p[c] = z0 * wv.x + z1 * wv.y + z2 * wv.z + z3 * wv.w;
        }
        #pragma unroll
        for (int off = 16; off; off >>= 1) {
            #pragma unroll
            for (int c = 0; c < C_OUT; c++)
                p[c] += __shfl_xor_sync(0xffffffffu, p[c], off);
        }
        int r = row0 + row;
        if (lane < C_OUT && r < nrows)
            yx[(size_t)(base_out + r) * C_OUT + lane] = p[lane];
    }
}

// ------------------------------ CSR build -----------------------------------
__global__ void __launch_bounds__(256) hist2_kernel(
    const int* __restrict__ rowsA, int E1, int* __restrict__ cntA,
    const int* __restrict__ rowsP, int E2, int* __restrict__ cntP) {
    int i = blockIdx.x * 256 + threadIdx.x;
    if (i < E1) atomicAdd(&cntA[__ldg(&rowsA[i])], 1);
    if (i < E2) atomicAdd(&cntP[__ldg(&rowsP[i]) - N_A], 1);
}

__global__ void __launch_bounds__(256) scan1_kernel(
    const int* __restrict__ cntA, int nA, int* __restrict__ rpA, int* __restrict__ bsumA, int nbA,
    const int* __restrict__ cntP, int nP, int* __restrict__ rpP, int* __restrict__ bsumP) {
    __shared__ int wsum[8];
    const int* cnt; int n; int* rp; int* bsum; int blk;
    if ((int)blockIdx.x < nbA) { cnt = cntA; n = nA; rp = rpA; bsum = bsumA; blk = blockIdx.x; }
    else                       { cnt = cntP; n = nP; rp = rpP; bsum = bsumP; blk = blockIdx.x - nbA; }
    const int base = blk * 2048;
    const int t = threadIdx.x;
    int v[8]; int s = 0;
    #pragma unroll
    for (int i = 0; i < 8; i++) {
        int idx = base + t * 8 + i;
        int c = (idx < n) ? __ldg(&cnt[idx]) : 0;
        v[i] = s; s += c;
    }
    int lane = t & 31, w = t >> 5;
    int p = s;
    #pragma unroll
    for (int o = 1; o < 32; o <<= 1) {
        int q = __shfl_up_sync(0xffffffffu, p, o);
        if (lane >= o) p += q;
    }
    if (lane == 31) wsum[w] = p;
    __syncthreads();
    if (t < 8) {
        int ws = wsum[t];
        int pp = ws;
        #pragma unroll
        for (int o = 1; o < 8; o <<= 1) {
            int q = __shfl_up_sync(0xffu, pp, o);
            if (t >= o) pp += q;
        }
        wsum[t] = pp - ws;
        if (t == 7) bsum[blk] = pp;
    }
    __syncthreads();
    int texcl = (p - s) + wsum[w];
    #pragma unroll
    for (int i = 0; i < 8; i++) {
        int idx = base + t * 8 + i;
        if (idx < n) rp[idx] = texcl + v[i];
    }
}

__global__ void __launch_bounds__(256) scan2_kernel(
    int* __restrict__ bsumA, int nbA, int* __restrict__ bsumP, int nbP) {
    __shared__ int sh[256];
    int* bsum = blockIdx.x == 0 ? bsumA : bsumP;
    int nb    = blockIdx.x == 0 ? nbA   : nbP;
    int t = threadIdx.x;
    int v = (t < nb) ? bsum[t] : 0;
    sh[t] = v; __syncthreads();
    #pragma unroll
    for (int o = 1; o < 256; o <<= 1) {
        int q = (t >= o) ? sh[t - o] : 0;
        __syncthreads();
        sh[t] += q;
        __syncthreads();
    }
    if (t < nb) bsum[t] = sh[t] - v;
}

__global__ void __launch_bounds__(256) scan3_kernel(
    const int* __restrict__ bsumA, int nA, int* __restrict__ rpA, int* __restrict__ offsA,
    const int* __restrict__ cntA, int ngA,
    const int* __restrict__ bsumP, int nP, int* __restrict__ rpP, int* __restrict__ offsP,
    const int* __restrict__ cntP) {
    const int* bsum; int n; int* rp; int* offs; const int* cnt; int idx;
    if ((int)blockIdx.x < ngA) {
        bsum = bsumA; n = nA; rp = rpA; offs = offsA; cnt = cntA;
        idx = blockIdx.x * 256 + threadIdx.x;
    } else {
        bsum = bsumP; n = nP; rp = rpP; offs = offsP; cnt = cntP;
        idx = (blockIdx.x - ngA) * 256 + threadIdx.x;
    }
    if (idx < n) {
        int v = rp[idx] + __ldg(&bsum[idx >> 11]);
        rp[idx] = v;
        offs[idx] = v;
        if (idx == n - 1) rp[n] = v + __ldg(&cnt[idx]);
    }
}

__global__ void __launch_bounds__(256) scatter2_kernel(
    const int* __restrict__ rowsA, const int* __restrict__ colsA,
    const float* __restrict__ valsA, int E1, int* __restrict__ offsA, uint2* __restrict__ ecvA,
    int* __restrict__ cntA,
    const int* __restrict__ rowsP, const int* __restrict__ colsP,
    const float* __restrict__ valsP, int E2, int* __restrict__ offsP, uint2* __restrict__ ecvP,
    int* __restrict__ cntP) {
    int i = blockIdx.x * 256 + threadIdx.x;
    if (i < N_A) cntA[i] = 0;
    if (i < N_P) cntP[i] = 0;
    if (i < E1) {
        int r = __ldg(&rowsA[i]);
        int pos = atomicAdd(&offsA[r], 1);
        ecvA[pos] = make_uint2((unsigned)(__ldg(&colsA[i]) - N_A), __float_as_uint(__ldg(&valsA[i])));
    }
    if (i < E2) {
        int r = __ldg(&rowsP[i]) - N_A;
        int pos = atomicAdd(&offsP[r], 1);
        ecvP[pos] = make_uint2((unsigned)__ldg(&colsP[i]), __float_as_uint(__ldg(&valsP[i])));
    }
}

// ---------------- 16-dim hop-1 SpMM (A + P in one grid) ----------------------
__global__ void __launch_bounds__(256) spmm_hop1_y_kernel(
    const int* __restrict__ rpA, const uint2* __restrict__ ecvA,
    const float4* __restrict__ srcA, float4* __restrict__ dstA,
    const int* __restrict__ rpP, const uint2* __restrict__ ecvP,
    const float4* __restrict__ srcP, float4* __restrict__ dstP) {
    int g = (int)((blockIdx.x * 256u + threadIdx.x) >> 5);
    if (g >= N_TOT) return;
    int lane = threadIdx.x & 31, grp = lane >> 2, q = lane & 3;
    const int* rp; const uint2* ecv; const float4* src; float4* dst; int r;
    if (g < N_A) { rp = rpA; ecv = ecvA; src = srcA; dst = dstA; r = g; }
    else         { rp = rpP; ecv = ecvP; src = srcP; dst = dstP; r = g - N_A; }
    int s = __ldg(&rp[r]), e = __ldg(&rp[r + 1]);
    float4 a = gather_y(ecv, src, s, e, grp, q);
    if (grp == 0) dst[(size_t)r * 4 + q] = a;
}

// ---------- 16-dim hop-2 fused with combine (pass 1: -> y1) ------------------
__global__ void __launch_bounds__(256) spmm_fused_y_kernel(
    const int* __restrict__ rpA, const uint2* __restrict__ ecvA,
    const int* __restrict__ rpP, const uint2* __restrict__ ecvP,
    const float4* __restrict__ yhA, const float4* __restrict__ yhP,
    const float4* __restrict__ yx, float4* __restrict__ y1,
    const float* __restrict__ coe) {
    int g = (int)((blockIdx.x * 256u + threadIdx.x) >> 5);
    if (g >= N_TOT) return;
    int lane = threadIdx.x & 31, grp = lane >> 2, q = lane & 3;
    const int* rp; const uint2* ecv; const float4* yh_src; const float4* yh_own;
    int r, c_own, c_hop;
    if (g < N_A) { rp = rpA; ecv = ecvA; yh_src = yhP; yh_own = yhA; r = g;       c_own = 1; c_hop = 3; }
    else         { rp = rpP; ecv = ecvP; yh_src = yhA; yh_own = yhP; r = g - N_A; c_own = 2; c_hop = 4; }
    int s = __ldg(&rp[r]), e = __ldg(&rp[r + 1]);
    float4 w = gather_y(ecv, yh_src, s, e, grp, q);
    if (grp == 0) {
        size_t R = (size_t)g;
        float c0 = __ldg(&coe[0]);
        float cw = __ldg(&coe[c_own]);
        float ch = __ldg(&coe[c_hop]);
        float4 xv = __ldg(yx + R * 4 + q);
        float4 hv = __ldg(yh_own + (size_t)r * 4 + q);
        float4 o;
        o.x = c0 * xv.x + cw * hv.x + ch * w.x;
        o.y = c0 * xv.y + cw * hv.y + ch * w.y;
        o.z = c0 * xv.z + cw * hv.z + ch * w.z;
        o.w = c0 * xv.w + cw * hv.w + ch * w.w;
        y1[R * 4 + q] = o;
    }
}

// ----- 16-dim hop-2 fused with combine + bias (pass 2: -> out) ---------------
__global__ void __launch_bounds__(256) spmm_fused_out_y_kernel(
    const int* __restrict__ rpA, const uint2* __restrict__ ecvA,
    const int* __restrict__ rpP, const uint2* __restrict__ ecvP,
    const float4* __restrict__ yhA, const float4* __restrict__ yhP,
    const float4* __restrict__ y1, float4* __restrict__ out,
    const float* __restrict__ coe, const float* __restrict__ b2) {
    int g = (int)((blockIdx.x * 256u + threadIdx.x) >> 5);
    if (g >= N_TOT) return;
    int lane = threadIdx.x & 31, grp = lane >> 2, q = lane & 3;
    const int* rp; const uint2* ecv; const float4* yh_src; const float4* yh_own;
    int r, c_own, c_hop;
    if (g < N_A) { rp = rpA; ecv = ecvA; yh_src = yhP; yh_own = yhA; r = g;       c_own = 2; c_hop = 4; }
    else         { rp = rpP; ecv = ecvP; yh_src = yhA; yh_own = yhP; r = g - N_A; c_own = 1; c_hop = 3; }
    int s = __ldg(&rp[r]), e = __ldg(&rp[r + 1]);
    float4 w = gather_y(ecv, yh_src, s, e, grp, q);
    if (grp == 0) {
        size_t R = (size_t)g;
        float c0 = __ldg(&coe[0]);
        float cw = __ldg(&coe[c_own]);
        float ch = __ldg(&coe[c_hop]);
        float4 xv = __ldg(y1 + R * 4 + q);
        float4 hv = __ldg(yh_own + (size_t)r * 4 + q);
        float4 bb = __ldg((const float4*)b2 + q);
        float4 o;
        o.x = c0 * xv.x + cw * hv.x + ch * w.x + bb.x;
        o.y = c0 * xv.y + cw * hv.y + ch * w.y + bb.y;
        o.z = c0 * xv.z + cw * hv.z + ch * w.z + bb.z;
        o.w = c0 * xv.w + cw * hv.w + ch * w.w + bb.w;
        out[R * 4 + q] = o;
    }
}

// ----------------------------------- launch ---------------------------------
extern "C" void kernel_launch(void* const* d_in, const int* in_sizes, int n_in,
                              void* d_out, int out_size) {
    const float* x0      = (const float*)d_in[0];
    const float* x1      = (const float*)d_in[1];
    const float* vals_ap = (const float*)d_in[2];
    const float* vals_pa = (const float*)d_in[3];
    const int*   rows_ap = (const int*)  d_in[4];
    const int*   cols_ap = (const int*)  d_in[5];
    const int*   rows_pa = (const int*)  d_in[6];
    const int*   cols_pa = (const int*)  d_in[7];
    const float* Wp0     = (const float*)d_in[8];
    const float* Wp1     = (const float*)d_in[9];
    const float* W1      = (const float*)d_in[10];
    const float* b1      = (const float*)d_in[11];
    const float* W2      = (const float*)d_in[12];
    const float* b2      = (const float*)d_in[13];
    const float* coe     = (const float*)d_in[14];
    float* out = (float*)d_out;

    const int E1 = in_sizes[2];
    const int E2 = in_sizes[3];

    float *pW0c, *pW1c, *pyx, *py1, *pyhA, *pyhP;
    uint2 *pecvA, *pecvP;
    int *pcntA, *pcntP, *prpA, *prpP, *poffA, *poffP, *pbA, *pbP;
    cudaGetSymbolAddress((void**)&pyx,   g_yx);
    cudaGetSymbolAddress((void**)&py1,   g_y1);
    cudaGetSymbolAddress((void**)&pyhA,  g_yhA);
    cudaGetSymbolAddress((void**)&pyhP,  g_yhP);
    cudaGetSymbolAddress((void**)&pW0c,  g_W0c);
    cudaGetSymbolAddress((void**)&pW1c,  g_W1c);
    cudaGetSymbolAddress((void**)&pcntA, g_cntA);
    cudaGetSymbolAddress((void**)&pcntP, g_cntP);
    cudaGetSymbolAddress((void**)&prpA,  g_rpA);
    cudaGetSymbolAddress((void**)&prpP,  g_rpP);
    cudaGetSymbolAddress((void**)&poffA, g_offA);
    cudaGetSymbolAddress((void**)&poffP, g_offP);
    cudaGetSymbolAddress((void**)&pbA,   g_bsumA);
    cudaGetSymbolAddress((void**)&pbP,   g_bsumP);
    cudaGetSymbolAddress((void**)&pecvA, g_ecvA);
    cudaGetSymbolAddress((void**)&pecvP, g_ecvP);

    const int nbA = (N_A + 2047) / 2048;
    const int nbP = (N_P + 2047) / 2048;
    const int ngA = (N_A + 255) / 256;
    const int ngP = (N_P + 255) / 256;
    const int gT  = (int)(((size_t)N_TOT * 32 + 255) / 256);
    const int Emax = E1 > E2 ? E1 : E2;

    static cudaStream_t s2 = nullptr;
    static cudaEvent_t evFork = nullptr, evCsr = nullptr;
    if (s2 == nullptr) {
        cudaStreamCreateWithFlags(&s2, cudaStreamNonBlocking);
        cudaEventCreateWithFlags(&evFork, cudaEventDisableTiming);
        cudaEventCreateWithFlags(&evCsr,  cudaEventDisableTiming);
    }
    cudaFuncSetAttribute(proj_norm_wmma_kernel,
                         cudaFuncAttributeMaxDynamicSharedMemorySize, PROJ_SMEM);

    // fork: CSR build on s2 concurrent with wcomb+projection on main
    cudaEventRecord(evFork, 0);
    cudaStreamWaitEvent(s2, evFork, 0);

    wcomb2_kernel<<<2 * D, D>>>(Wp0, Wp1, W1, pW0c, pW1c);
    proj_norm_wmma_kernel<<<(N_A + 63) / 64 + (N_P + 63) / 64, 256, PROJ_SMEM>>>(
        x0, x1, pW0c, pW1c, b1, W2, pyx);

    hist2_kernel<<<(Emax + 255) / 256, 256, 0, s2>>>(rows_ap, E1, pcntA, rows_pa, E2, pcntP);
    scan1_kernel<<<nbA + nbP, 256, 0, s2>>>(pcntA, N_A, prpA, pbA, nbA, pcntP, N_P, prpP, pbP);
    scan2_kernel<<<2, 256, 0, s2>>>(pbA, nbA, pbP, nbP);
    scan3_kernel<<<ngA + ngP, 256, 0, s2>>>(pbA, N_A, prpA, poffA, pcntA, ngA,
                                            pbP, N_P, prpP, poffP, pcntP);
    scatter2_kernel<<<(Emax + 255) / 256, 256, 0, s2>>>(
        rows_ap, cols_ap, vals_ap, E1, poffA, pecvA, pcntA,
        rows_pa, cols_pa, vals_pa, E2, poffP, pecvP, pcntP);
    cudaEventRecord(evCsr, s2);
    cudaStreamWaitEvent(0, evCsr, 0);

    // ---------------- pass 1 (first_order = AP, PA), all 16-dim --------------
    spmm_hop1_y_kernel<<<gT, 256>>>(prpA, pecvA, (const float4*)(pyx + (size_t)N_A * C_OUT),
                                    (float4*)pyhA,
                                    prpP, pecvP, (const float4*)pyx, (float4*)pyhP);
    spmm_fused_y_kernel<<<gT, 256>>>(prpA, pecvA, prpP, pecvP,
                                     (const float4*)pyhA, (const float4*)pyhP,
                                     (const float4*)pyx, (float4*)py1, coe);

    // ---------------- pass 2 (first_order = PA, AP), all 16-dim --------------
    spmm_hop1_y_kernel<<<gT, 256>>>(prpA, pecvA, (const float4*)(py1 + (size_t)N_A * C_OUT),
                                    (float4*)pyhA,
                                    prpP, pecvP, (const float4*)py1, (float4*)pyhP);
    spmm_fused_out_y_kernel<<<gT, 256>>>(prpA, pecvA, prpP, pecvP,
                                         (const float4*)pyhA, (const float4*)pyhP,
                                         (const float4*)py1, (float4*)out, coe, b2);
}